// round 3
// baseline (speedup 1.0000x reference)
#include <cuda_runtime.h>
#include <cstdint>

// ---------------------------------------------------------------------------
// Problem constants
// ---------------------------------------------------------------------------
constexpr int B     = 8;
constexpr int L     = 256;
constexpr int D     = 768;
constexpr int H     = 12;
constexpr int DH    = 64;          // D / H
constexpr int M     = B * L;       // 2048 total query rows
constexpr int NDICT = 16384;
constexpr int KP    = 8;           // top-k
constexpr int SKG   = L * KP;      // 2048 kv rows per batch (cross-attn)
constexpr int BH    = B * H;       // 96

// ---------------------------------------------------------------------------
// Device-global scratch (no dynamic allocation allowed)
// ---------------------------------------------------------------------------
__device__ float g_tnorm[(size_t)M * D];
__device__ float g_gnorm[(size_t)NDICT * D];
__device__ float g_sim[(size_t)M * NDICT];
__device__ int   g_topk[(size_t)M * KP];
__device__ float g_gfeats[(size_t)B * SKG * D];
__device__ float g_q[(size_t)M * D];
__device__ float g_k[(size_t)B * SKG * D];
__device__ float g_v[(size_t)B * SKG * D];
__device__ float g_scores[(size_t)BH * L * SKG];
__device__ float g_ctx[(size_t)M * D];
__device__ float g_proj[(size_t)M * D];
__device__ float g_ll[(size_t)M * D];
__device__ float g_lg[(size_t)M * D];

#define DEV_INLINE __device__ __forceinline__

DEV_INLINE float blockReduceSum(float v, float* sh) {
    int tid = threadIdx.x;
    sh[tid] = v; __syncthreads();
    #pragma unroll
    for (int s = 128; s > 0; s >>= 1) {
        if (tid < s) sh[tid] += sh[tid + s];
        __syncthreads();
    }
    float r = sh[0]; __syncthreads();
    return r;
}

DEV_INLINE float blockReduceMax(float v, float* sh) {
    int tid = threadIdx.x;
    sh[tid] = v; __syncthreads();
    #pragma unroll
    for (int s = 128; s > 0; s >>= 1) {
        if (tid < s) sh[tid] = fmaxf(sh[tid], sh[tid + s]);
        __syncthreads();
    }
    float r = sh[0]; __syncthreads();
    return r;
}

// ---------------------------------------------------------------------------
// Row L2-normalize: y = x / ||x||  (one block per row, D = 768, 256 threads)
// ---------------------------------------------------------------------------
__global__ __launch_bounds__(256) void rownorm_kernel(
    const float* __restrict__ x, float* __restrict__ y) {
    __shared__ float sh[256];
    size_t row = blockIdx.x;
    int tid = threadIdx.x;
    const float* xr = x + row * D;
    float* yr = y + row * D;
    float v0 = xr[tid], v1 = xr[tid + 256], v2 = xr[tid + 512];
    float ss = blockReduceSum(v0 * v0 + v1 * v1 + v2 * v2, sh);
    float inv = rsqrtf(ss);
    yr[tid] = v0 * inv; yr[tid + 256] = v1 * inv; yr[tid + 512] = v2 * inv;
}

// ---------------------------------------------------------------------------
// Generic SGEMM: C[M,N] = A[M,K] * op(B) (+ bias[N])
//   TB=false: B is [K,N] row-major (NN)
//   TB=true : B is [N,K] row-major (NT)
// 128x128 tile, BK=8, 256 threads, 8x8 microtile. All dims multiples of (128,128,8).
// ---------------------------------------------------------------------------
template <bool TB, bool HAS_BIAS>
__global__ __launch_bounds__(256) void sgemm128(
    const float* __restrict__ A, const float* __restrict__ Bm,
    const float* __restrict__ bias, float* __restrict__ C,
    int Mdim, int Ndim, int Kdim) {
    __shared__ float As[8][128];
    __shared__ float Bs[8][128];
    int tid = threadIdx.x;
    int row0 = blockIdx.y * 128;
    int col0 = blockIdx.x * 128;
    int tx = tid & 15, ty = tid >> 4;

    float acc[8][8];
    #pragma unroll
    for (int i = 0; i < 8; ++i)
        #pragma unroll
        for (int j = 0; j < 8; ++j) acc[i][j] = 0.f;

    int arow = tid >> 1, acol = (tid & 1) * 4;   // A / B(NT) load pattern
    int brow = tid >> 5, bcol = (tid & 31) * 4;  // B(NN) load pattern

    for (int k0 = 0; k0 < Kdim; k0 += 8) {
        float4 a4 = *(const float4*)(A + (size_t)(row0 + arow) * Kdim + k0 + acol);
        As[acol + 0][arow] = a4.x; As[acol + 1][arow] = a4.y;
        As[acol + 2][arow] = a4.z; As[acol + 3][arow] = a4.w;
        if (TB) {
            float4 b4 = *(const float4*)(Bm + (size_t)(col0 + arow) * Kdim + k0 + acol);
            Bs[acol + 0][arow] = b4.x; Bs[acol + 1][arow] = b4.y;
            Bs[acol + 2][arow] = b4.z; Bs[acol + 3][arow] = b4.w;
        } else {
            float4 b4 = *(const float4*)(Bm + (size_t)(k0 + brow) * Ndim + col0 + bcol);
            *(float4*)&Bs[brow][bcol] = b4;
        }
        __syncthreads();
        #pragma unroll
        for (int kk = 0; kk < 8; ++kk) {
            float ar[8], br[8];
            #pragma unroll
            for (int i = 0; i < 8; ++i) ar[i] = As[kk][ty * 8 + i];
            #pragma unroll
            for (int j = 0; j < 8; ++j) br[j] = Bs[kk][tx * 8 + j];
            #pragma unroll
            for (int i = 0; i < 8; ++i)
                #pragma unroll
                for (int j = 0; j < 8; ++j)
                    acc[i][j] = fmaf(ar[i], br[j], acc[i][j]);
        }
        __syncthreads();
    }

    #pragma unroll
    for (int i = 0; i < 8; ++i) {
        size_t crow = (size_t)(row0 + ty * 8 + i);
        #pragma unroll
        for (int j = 0; j < 8; ++j) {
            int ccol = col0 + tx * 8 + j;
            float val = acc[i][j];
            if (HAS_BIAS) val += bias[ccol];
            C[crow * Ndim + ccol] = val;
        }
    }
}

// ---------------------------------------------------------------------------
// Top-8 per row of sim (one block per row; per-thread top8 + smem tree merge)
// jax.lax.top_k semantics: sorted desc, ties -> smaller index first.
// ---------------------------------------------------------------------------
__global__ __launch_bounds__(256) void topk_kernel(
    const float* __restrict__ sim, int* __restrict__ out) {
    __shared__ float sv[256][KP];
    __shared__ int   si[256][KP];
    int row = blockIdx.x;
    int tid = threadIdx.x;
    const float* s = sim + (size_t)row * NDICT;
    float tv[KP]; int ti[KP];
    #pragma unroll
    for (int i = 0; i < KP; ++i) { tv[i] = -3.4e38f; ti[i] = 0x7fffffff; }
    for (int j = tid; j < NDICT; j += 256) {
        float v = s[j];
        if (v > tv[KP - 1]) {
            int p = KP - 1;
            while (p > 0 && v > tv[p - 1]) { tv[p] = tv[p - 1]; ti[p] = ti[p - 1]; --p; }
            tv[p] = v; ti[p] = j;
        }
    }
    #pragma unroll
    for (int i = 0; i < KP; ++i) { sv[tid][i] = tv[i]; si[tid][i] = ti[i]; }
    __syncthreads();
    for (int st = 128; st >= 1; st >>= 1) {
        if (tid < st) {
            float mv[KP]; int mi[KP]; int pa = 0, pb = 0;
            #pragma unroll
            for (int o = 0; o < KP; ++o) {
                float va = sv[tid][pa], vb = sv[tid + st][pb];
                int ia = si[tid][pa], ib = si[tid + st][pb];
                bool takeA = (va > vb) || (va == vb && ia <= ib);
                if (takeA) { mv[o] = va; mi[o] = ia; ++pa; }
                else       { mv[o] = vb; mi[o] = ib; ++pb; }
            }
            #pragma unroll
            for (int o = 0; o < KP; ++o) { sv[tid][o] = mv[o]; si[tid][o] = mi[o]; }
        }
        __syncthreads();
    }
    if (tid < KP) out[(size_t)row * KP + tid] = si[0][tid];
}

// ---------------------------------------------------------------------------
// Gather retrieved prototypes (UNnormalized dict rows) into [B*SKG, D]
// ---------------------------------------------------------------------------
__global__ __launch_bounds__(256) void gather_kernel(
    const float* __restrict__ dict, const int* __restrict__ topk,
    float* __restrict__ gfeats) {
    int r = blockIdx.x;                 // 0 .. B*SKG-1
    int b = r >> 11;                    // / 2048
    int pos = r & 2047;
    int idx = topk[((size_t)(b * L + (pos >> 3))) * KP + (pos & 7)];
    const float* src = dict + (size_t)idx * D;
    float* dst = gfeats + (size_t)r * D;
    for (int j = threadIdx.x; j < D; j += 256) dst[j] = src[j];
}

// ---------------------------------------------------------------------------
// Attention scores: S[bh, q, k] = (Q_bh[q,:] . K_bh[k,:]) / 8
// grid: (Sk/64, Sq/64=4, BH). Q,K live in [rows, D] buffers with head slice.
// ---------------------------------------------------------------------------
__global__ __launch_bounds__(256) void attn_scores_kernel(
    const float* __restrict__ q, const float* __restrict__ k,
    float* __restrict__ scores, int Sk) {
    __shared__ float Qs[64][65];
    __shared__ float Ks[64][65];
    int bh = blockIdx.z;
    int b = bh / H, h = bh % H;
    int q0 = blockIdx.y * 64, k0 = blockIdx.x * 64;
    const float* Qb = q + (size_t)(b * L) * D + h * DH;
    const float* Kb = k + (size_t)(b * Sk) * D + h * DH;
    int tid = threadIdx.x;
    for (int t = tid; t < 64 * 16; t += 256) {
        int r = t >> 4, c4 = (t & 15) << 2;
        float4 qa = *(const float4*)(Qb + (size_t)(q0 + r) * D + c4);
        Qs[r][c4] = qa.x; Qs[r][c4 + 1] = qa.y; Qs[r][c4 + 2] = qa.z; Qs[r][c4 + 3] = qa.w;
        float4 ka = *(const float4*)(Kb + (size_t)(k0 + r) * D + c4);
        Ks[r][c4] = ka.x; Ks[r][c4 + 1] = ka.y; Ks[r][c4 + 2] = ka.z; Ks[r][c4 + 3] = ka.w;
    }
    __syncthreads();
    int tx = tid & 15, ty = tid >> 4;
    float acc[4][4];
    #pragma unroll
    for (int i = 0; i < 4; ++i)
        #pragma unroll
        for (int j = 0; j < 4; ++j) acc[i][j] = 0.f;
    #pragma unroll 8
    for (int kk = 0; kk < 64; ++kk) {
        float a[4], bb[4];
        #pragma unroll
        for (int i = 0; i < 4; ++i) a[i] = Qs[ty * 4 + i][kk];
        #pragma unroll
        for (int j = 0; j < 4; ++j) bb[j] = Ks[tx * 4 + j][kk];
        #pragma unroll
        for (int i = 0; i < 4; ++i)
            #pragma unroll
            for (int j = 0; j < 4; ++j)
                acc[i][j] = fmaf(a[i], bb[j], acc[i][j]);
    }
    float* Sb = scores + (size_t)bh * L * Sk;
    #pragma unroll
    for (int i = 0; i < 4; ++i)
        #pragma unroll
        for (int j = 0; j < 4; ++j)
            Sb[(size_t)(q0 + ty * 4 + i) * Sk + (k0 + tx * 4 + j)] = acc[i][j] * 0.125f;
}

// ---------------------------------------------------------------------------
// Row softmax in-place over [BH*L] rows of length Sk (256 or 2048)
// ---------------------------------------------------------------------------
__global__ __launch_bounds__(256) void softmax_kernel(float* __restrict__ s, int Sk) {
    __shared__ float sh[256];
    size_t row = blockIdx.x;
    float* p = s + row * (size_t)Sk;
    int tid = threadIdx.x;
    int per = Sk >> 8;                 // 1 or 8
    float vals[8];
    float m = -3.4e38f;
    for (int t = 0; t < per; ++t) { vals[t] = p[tid + (t << 8)]; m = fmaxf(m, vals[t]); }
    m = blockReduceMax(m, sh);
    float sum = 0.f;
    for (int t = 0; t < per; ++t) { vals[t] = expf(vals[t] - m); sum += vals[t]; }
    sum = blockReduceSum(sum, sh);
    float inv = 1.0f / sum;
    for (int t = 0; t < per; ++t) p[tid + (t << 8)] = vals[t] * inv;
}

// ---------------------------------------------------------------------------
// Context: ctx[b*L+q, h*64+c] = sum_k P[bh,q,k] * V[b*Sk+k, h*64+c]
// grid: (Sq/64=4, BH)
// ---------------------------------------------------------------------------
__global__ __launch_bounds__(256) void attn_ctx_kernel(
    const float* __restrict__ probs, const float* __restrict__ v,
    float* __restrict__ ctx, int Sk) {
    __shared__ float Ps[64][65];
    __shared__ float Vs[64][64];
    int bh = blockIdx.y;
    int b = bh / H, h = bh % H;
    int q0 = blockIdx.x * 64;
    const float* Pb = probs + (size_t)bh * L * Sk;
    const float* Vb = v + (size_t)(b * Sk) * D + h * DH;
    int tid = threadIdx.x;
    int tx = tid & 15, ty = tid >> 4;
    float acc[4][4];
    #pragma unroll
    for (int i = 0; i < 4; ++i)
        #pragma unroll
        for (int j = 0; j < 4; ++j) acc[i][j] = 0.f;
    for (int kt = 0; kt < Sk; kt += 64) {
        for (int t = tid; t < 64 * 16; t += 256) {
            int r = t >> 4, c4 = (t & 15) << 2;
            float4 pa = *(const float4*)(Pb + (size_t)(q0 + r) * Sk + kt + c4);
            Ps[r][c4] = pa.x; Ps[r][c4 + 1] = pa.y; Ps[r][c4 + 2] = pa.z; Ps[r][c4 + 3] = pa.w;
            float4 va = *(const float4*)(Vb + (size_t)(kt + r) * D + c4);
            *(float4*)&Vs[r][c4] = va;
        }
        __syncthreads();
        #pragma unroll 8
        for (int kk = 0; kk < 64; ++kk) {
            float a[4], bb[4];
            #pragma unroll
            for (int i = 0; i < 4; ++i) a[i] = Ps[ty * 4 + i][kk];
            #pragma unroll
            for (int j = 0; j < 4; ++j) bb[j] = Vs[kk][tx * 4 + j];
            #pragma unroll
            for (int i = 0; i < 4; ++i)
                #pragma unroll
                for (int j = 0; j < 4; ++j)
                    acc[i][j] = fmaf(a[i], bb[j], acc[i][j]);
        }
        __syncthreads();
    }
    #pragma unroll
    for (int i = 0; i < 4; ++i)
        #pragma unroll
        for (int j = 0; j < 4; ++j)
            ctx[(size_t)(b * L + q0 + ty * 4 + i) * D + h * DH + tx * 4 + j] = acc[i][j];
}

// ---------------------------------------------------------------------------
// y = LayerNorm(x + residual) * g + beta   (bias already folded into x)
// ---------------------------------------------------------------------------
__global__ __launch_bounds__(256) void residual_ln_kernel(
    const float* __restrict__ x, const float* __restrict__ res,
    const float* __restrict__ g, const float* __restrict__ beta,
    float* __restrict__ out) {
    __shared__ float sh[256];
    size_t base = (size_t)blockIdx.x * D;
    int tid = threadIdx.x;
    float v[3];
    #pragma unroll
    for (int t = 0; t < 3; ++t) {
        int i = tid + (t << 8);
        v[t] = x[base + i] + res[base + i];
    }
    float mean = blockReduceSum(v[0] + v[1] + v[2], sh) * (1.0f / 768.0f);
    float d0 = v[0] - mean, d1 = v[1] - mean, d2 = v[2] - mean;
    float var = blockReduceSum(d0 * d0 + d1 * d1 + d2 * d2, sh) * (1.0f / 768.0f);
    float inv = rsqrtf(var + 1e-12f);
    #pragma unroll
    for (int t = 0; t < 3; ++t) {
        int i = tid + (t << 8);
        out[base + i] = (v[t] - mean) * inv * g[i] + beta[i];
    }
}

// ---------------------------------------------------------------------------
// Final: out_ln = LN(ll+lg); gate = sigmoid(out_ln.aug_w + aug_b + local.ori_w + ori_b)
//        result = gate*out_ln + (1-gate)*local
// ---------------------------------------------------------------------------
__global__ __launch_bounds__(256) void final_kernel(
    const float* __restrict__ ll, const float* __restrict__ lg,
    const float* __restrict__ local, const float* __restrict__ g,
    const float* __restrict__ beta, const float* __restrict__ aug_w,
    const float* __restrict__ aug_b, const float* __restrict__ ori_w,
    const float* __restrict__ ori_b, float* __restrict__ out) {
    __shared__ float sh[256];
    size_t base = (size_t)blockIdx.x * D;
    int tid = threadIdx.x;
    float s[3], lf[3];
    #pragma unroll
    for (int t = 0; t < 3; ++t) {
        int i = tid + (t << 8);
        s[t] = ll[base + i] + lg[base + i];
        lf[t] = local[base + i];
    }
    float mean = blockReduceSum(s[0] + s[1] + s[2], sh) * (1.0f / 768.0f);
    float d0 = s[0] - mean, d1 = s[1] - mean, d2 = s[2] - mean;
    float var = blockReduceSum(d0 * d0 + d1 * d1 + d2 * d2, sh) * (1.0f / 768.0f);
    float inv = rsqrtf(var + 1e-12f);
    float o[3];
    float dsum = 0.f;
    #pragma unroll
    for (int t = 0; t < 3; ++t) {
        int i = tid + (t << 8);
        o[t] = (s[t] - mean) * inv * g[i] + beta[i];
        dsum += o[t] * aug_w[i] + lf[t] * ori_w[i];
    }
    dsum = blockReduceSum(dsum, sh);
    float gate = 1.0f / (1.0f + expf(-(dsum + aug_b[0] + ori_b[0])));
    #pragma unroll
    for (int t = 0; t < 3; ++t) {
        int i = tid + (t << 8);
        out[base + i] = gate * o[t] + (1.0f - gate) * lf[t];
    }
}

// ---------------------------------------------------------------------------
// Host launcher
// ---------------------------------------------------------------------------
extern "C" void kernel_launch(void* const* d_in, const int* in_sizes, int n_in,
                              void* d_out, int out_size) {
    (void)n_in; (void)out_size;
    const float* local = (const float*)d_in[0];
    const float* dict  = (const float*)d_in[1];

    // Two possible input orderings; disambiguate via element counts.
    // signature order: wq,bq,wk,bk,wv,bv,wo,bo,ln_g,ln_b per prefix; then
    //                  ln_g,ln_b,aug_w,aug_b,ori_w,ori_b
    // dict order:      wq,wk,wv,wo,bq,bk,bv,bo,ln_g,ln_b per prefix; then
    //                  ln_g,ln_b,aug_w,ori_w,aug_b,ori_b
    bool sig = (in_sizes[3] == 768);
    const float *W[2][4], *Bi[2][4], *LNG[2], *LNB[2];
    for (int p = 0; p < 2; ++p) {
        int base = 2 + p * 10;
        if (sig) {
            for (int j = 0; j < 4; ++j) {
                W[p][j]  = (const float*)d_in[base + 2 * j];
                Bi[p][j] = (const float*)d_in[base + 2 * j + 1];
            }
        } else {
            for (int j = 0; j < 4; ++j) {
                W[p][j]  = (const float*)d_in[base + j];
                Bi[p][j] = (const float*)d_in[base + 4 + j];
            }
        }
        LNG[p] = (const float*)d_in[base + 8];
        LNB[p] = (const float*)d_in[base + 9];
    }
    const float* ln_g = (const float*)d_in[22];
    const float* ln_b = (const float*)d_in[23];
    const float *aug_w, *aug_b, *ori_w, *ori_b;
    if (in_sizes[25] == 1) {        // signature order tail
        aug_w = (const float*)d_in[24]; aug_b = (const float*)d_in[25];
        ori_w = (const float*)d_in[26]; ori_b = (const float*)d_in[27];
    } else {                        // dict order tail
        aug_w = (const float*)d_in[24]; ori_w = (const float*)d_in[25];
        aug_b = (const float*)d_in[26]; ori_b = (const float*)d_in[27];
    }

    float *p_tnorm, *p_gnorm, *p_sim, *p_gfeats, *p_q, *p_k, *p_v;
    float *p_scores, *p_ctx, *p_proj, *p_ll, *p_lg;
    int* p_topk;
    cudaGetSymbolAddress((void**)&p_tnorm, g_tnorm);
    cudaGetSymbolAddress((void**)&p_gnorm, g_gnorm);
    cudaGetSymbolAddress((void**)&p_sim, g_sim);
    cudaGetSymbolAddress((void**)&p_topk, g_topk);
    cudaGetSymbolAddress((void**)&p_gfeats, g_gfeats);
    cudaGetSymbolAddress((void**)&p_q, g_q);
    cudaGetSymbolAddress((void**)&p_k, g_k);
    cudaGetSymbolAddress((void**)&p_v, g_v);
    cudaGetSymbolAddress((void**)&p_scores, g_scores);
    cudaGetSymbolAddress((void**)&p_ctx, g_ctx);
    cudaGetSymbolAddress((void**)&p_proj, g_proj);
    cudaGetSymbolAddress((void**)&p_ll, g_ll);
    cudaGetSymbolAddress((void**)&p_lg, g_lg);

    // 1) normalize
    rownorm_kernel<<<NDICT, 256>>>(dict, p_gnorm);
    rownorm_kernel<<<M, 256>>>(local, p_tnorm);

    // 2) sim = tnorm @ gnorm^T   [2048 x 16384]
    sgemm128<true, false><<<dim3(NDICT / 128, M / 128), 256>>>(
        p_tnorm, p_gnorm, nullptr, p_sim, M, NDICT, D);

    // 3) top-8 per row, 4) gather prototypes
    topk_kernel<<<M, 256>>>(p_sim, p_topk);
    gather_kernel<<<B * SKG, 256>>>(dict, p_topk, p_gfeats);

    dim3 gProj(D / 128, M / 128);         // (6,16)
    dim3 gProjBig(D / 128, (B * SKG) / 128); // (6,128)

    // ---- ll: self-attention over locals ----
    sgemm128<false, true><<<gProj, 256>>>(local, W[0][0], Bi[0][0], p_q, M, D, D);
    sgemm128<false, true><<<gProj, 256>>>(local, W[0][1], Bi[0][1], p_k, M, D, D);
    sgemm128<false, true><<<gProj, 256>>>(local, W[0][2], Bi[0][2], p_v, M, D, D);
    attn_scores_kernel<<<dim3(L / 64, L / 64, BH), 256>>>(p_q, p_k, p_scores, L);
    softmax_kernel<<<BH * L, 256>>>(p_scores, L);
    attn_ctx_kernel<<<dim3(L / 64, BH), 256>>>(p_scores, p_v, p_ctx, L);
    sgemm128<false, true><<<gProj, 256>>>(p_ctx, W[0][3], Bi[0][3], p_proj, M, D, D);
    residual_ln_kernel<<<M, 256>>>(p_proj, local, LNG[0], LNB[0], p_ll);

    // ---- lg: cross-attention to retrieved prototypes ----
    sgemm128<false, true><<<gProj, 256>>>(local, W[1][0], Bi[1][0], p_q, M, D, D);
    sgemm128<false, true><<<gProjBig, 256>>>(p_gfeats, W[1][1], Bi[1][1], p_k, B * SKG, D, D);
    sgemm128<false, true><<<gProjBig, 256>>>(p_gfeats, W[1][2], Bi[1][2], p_v, B * SKG, D, D);
    attn_scores_kernel<<<dim3(SKG / 64, L / 64, BH), 256>>>(p_q, p_k, p_scores, SKG);
    softmax_kernel<<<BH * L, 256>>>(p_scores, SKG);
    attn_ctx_kernel<<<dim3(L / 64, BH), 256>>>(p_scores, p_v, p_ctx, SKG);
    sgemm128<false, true><<<gProj, 256>>>(p_ctx, W[1][3], Bi[1][3], p_proj, M, D, D);
    residual_ln_kernel<<<M, 256>>>(p_proj, local, LNG[1], LNB[1], p_lg);

    // ---- final LN + gating ----
    final_kernel<<<M, 256>>>(p_ll, p_lg, local, ln_g, ln_b,
                             aug_w, aug_b, ori_w, ori_b, (float*)d_out);
}

// round 5
// speedup vs baseline: 2.0496x; 2.0496x over previous
#include <cuda_runtime.h>
#include <cstdint>

// ---------------------------------------------------------------------------
// Problem constants
// ---------------------------------------------------------------------------
constexpr int B     = 8;
constexpr int L     = 256;
constexpr int D     = 768;
constexpr int H     = 12;
constexpr int DH    = 64;          // D / H
constexpr int M     = B * L;       // 2048 total query rows
constexpr int NDICT = 16384;
constexpr int KP    = 8;           // top-k
constexpr int SKG   = L * KP;      // 2048 kv rows per batch (cross-attn)
constexpr int BH    = B * H;       // 96

// ---------------------------------------------------------------------------
// Device-global scratch (no dynamic allocation allowed)
// ---------------------------------------------------------------------------
__device__ float g_tnorm[(size_t)M * D];
__device__ float g_gnorm[(size_t)NDICT * D];
__device__ float g_sim[(size_t)M * NDICT];
__device__ int   g_topk[(size_t)M * KP];
__device__ float g_gfeats[(size_t)B * SKG * D];
__device__ float g_q[(size_t)M * D];
__device__ float g_k[(size_t)B * SKG * D];
__device__ float g_v[(size_t)B * SKG * D];
__device__ float g_scores[(size_t)BH * L * SKG];
__device__ float g_ctx[(size_t)M * D];
__device__ float g_proj[(size_t)M * D];
__device__ float g_ll[(size_t)M * D];
__device__ float g_lg[(size_t)M * D];

#define DEV_INLINE __device__ __forceinline__

DEV_INLINE float blockReduceSum(float v, float* sh) {
    int tid = threadIdx.x;
    sh[tid] = v; __syncthreads();
    #pragma unroll
    for (int s = 128; s > 0; s >>= 1) {
        if (tid < s) sh[tid] += sh[tid + s];
        __syncthreads();
    }
    float r = sh[0]; __syncthreads();
    return r;
}

DEV_INLINE float blockReduceMax(float v, float* sh) {
    int tid = threadIdx.x;
    sh[tid] = v; __syncthreads();
    #pragma unroll
    for (int s = 128; s > 0; s >>= 1) {
        if (tid < s) sh[tid] = fmaxf(sh[tid], sh[tid + s]);
        __syncthreads();
    }
    float r = sh[0]; __syncthreads();
    return r;
}

// ---------------------------------------------------------------------------
// tf32 helpers
// ---------------------------------------------------------------------------
DEV_INLINE uint32_t f2tf32(float x) {
    uint32_t u;
    asm("cvt.rna.tf32.f32 %0, %1;" : "=r"(u) : "f"(x));
    return u;
}

DEV_INLINE void mma_tf32(float& c0, float& c1, float& c2, float& c3,
                         uint32_t a0, uint32_t a1, uint32_t a2, uint32_t a3,
                         uint32_t b0, uint32_t b1) {
    asm volatile(
        "mma.sync.aligned.m16n8k8.row.col.f32.tf32.tf32.f32 "
        "{%0,%1,%2,%3}, {%4,%5,%6,%7}, {%8,%9}, {%0,%1,%2,%3};"
        : "+f"(c0), "+f"(c1), "+f"(c2), "+f"(c3)
        : "r"(a0), "r"(a1), "r"(a2), "r"(a3), "r"(b0), "r"(b1));
}

// ---------------------------------------------------------------------------
// tf32 tensor-core GEMM.
//   C[m,n] = alpha * A[m,:] . op(B)[:,n]  (+ bias[n])
//   TB=true : B is [N,K] row-major (NT)    TB=false: B is [K,N] row-major (NN)
//   SPLIT=true: 3xTF32 (hi/lo decomposition, ~fp32 accuracy)
// Batched over blockIdx.z: operand offset = (z/H)*SB + (z%H)*SH per operand.
// BM in {128}, BN in {128, 64}. BK = 32. 256 threads (8 warps).
// All of Mdim, Ndim multiples of BM/BN; Kdim multiple of 32.
// Dynamic smem: (SPLIT?2:1) * (ASZ + BSZ) * 4 bytes.
// ---------------------------------------------------------------------------
template <int BM, int BN, bool TB, bool SPLIT, bool HAS_BIAS>
__global__ __launch_bounds__(256) void tf32gemm(
    const float* __restrict__ Ag, const float* __restrict__ Bg,
    const float* __restrict__ bias, float* __restrict__ Cg,
    int Kdim, int lda, int ldb, int ldc,
    long aSB, long aSH, long bSB, long bSH, long cSB, long cSH,
    float alpha) {
    constexpr int BK = 32;
    constexpr int WN_CNT = (BN == 128) ? 4 : 2;
    constexpr int WM_CNT = 8 / WN_CNT;
    constexpr int WM = BM / WM_CNT;   // 64 or 32
    constexpr int WN = BN / WN_CNT;   // 32
    constexpr int MT = WM / 16;       // 4 or 2
    constexpr int NTL = WN / 8;       // 4
    constexpr int ASTR = 36;                       // [m][k] stride
    constexpr int BSTR = TB ? 36 : (BN + 8);       // [n][k] or [k][n]
    constexpr int ASZ = BM * ASTR;
    constexpr int BSZ = TB ? (BN * 36) : (BK * (BN + 8));

    extern __shared__ uint32_t dynsmem[];
    uint32_t* As = dynsmem;                               // [+ASZ lo if SPLIT]
    uint32_t* Bs = dynsmem + (SPLIT ? 2 : 1) * ASZ;       // [+BSZ lo if SPLIT]

    int tid = threadIdx.x;
    int lane = tid & 31, warp = tid >> 5;
    int wm = warp / WN_CNT, wn = warp % WN_CNT;
    int row0 = blockIdx.y * BM;
    int col0 = blockIdx.x * BN;
    int z = blockIdx.z;
    int zb = z / H, zh = z % H;

    const float* A = Ag + (size_t)zb * aSB + (size_t)zh * aSH;
    const float* Bp = Bg + (size_t)zb * bSB + (size_t)zh * bSH;
    float* C = Cg + (size_t)zb * cSB + (size_t)zh * cSH;

    float acc[MT][NTL][4];
    #pragma unroll
    for (int i = 0; i < MT; ++i)
        #pragma unroll
        for (int j = 0; j < NTL; ++j)
            #pragma unroll
            for (int c = 0; c < 4; ++c) acc[i][j][c] = 0.f;

    int aK = tid & 7;       // float4 index along k (A / NT-B loads)
    int aM = tid >> 3;      // 0..31
    constexpr int BV = BN / 4;            // float4 per NN-B row
    int bN = tid % BV;
    int bK = tid / BV;
    constexpr int BKSTEP = 256 / BV;

    for (int k0 = 0; k0 < Kdim; k0 += BK) {
        __syncthreads();
        // ---- load A tile (BMxBK), transpose-free [m][k] store ----
        #pragma unroll
        for (int mm = 0; mm < BM; mm += 32) {
            int r = mm + aM;
            float4 v = *(const float4*)(A + (size_t)(row0 + r) * lda + k0 + aK * 4);
            int base = r * ASTR + aK * 4;
            float vv[4] = {v.x, v.y, v.z, v.w};
            #pragma unroll
            for (int c = 0; c < 4; ++c) {
                uint32_t h = f2tf32(vv[c]);
                As[base + c] = h;
                if (SPLIT) As[ASZ + base + c] = f2tf32(vv[c] - __uint_as_float(h));
            }
        }
        // ---- load B tile ----
        if (TB) {
            #pragma unroll
            for (int nn = 0; nn < BN; nn += 32) {
                int r = nn + aM;
                float4 v = *(const float4*)(Bp + (size_t)(col0 + r) * ldb + k0 + aK * 4);
                int base = r * 36 + aK * 4;
                float vv[4] = {v.x, v.y, v.z, v.w};
                #pragma unroll
                for (int c = 0; c < 4; ++c) {
                    uint32_t h = f2tf32(vv[c]);
                    Bs[base + c] = h;
                    if (SPLIT) Bs[BSZ + base + c] = f2tf32(vv[c] - __uint_as_float(h));
                }
            }
        } else {
            #pragma unroll
            for (int kk = 0; kk < BK; kk += BKSTEP) {
                int r = kk + bK;
                float4 v = *(const float4*)(Bp + (size_t)(k0 + r) * ldb + col0 + bN * 4);
                int base = r * (BN + 8) + bN * 4;
                float vv[4] = {v.x, v.y, v.z, v.w};
                #pragma unroll
                for (int c = 0; c < 4; ++c) {
                    uint32_t h = f2tf32(vv[c]);
                    Bs[base + c] = h;
                    if (SPLIT) Bs[BSZ + base + c] = f2tf32(vv[c] - __uint_as_float(h));
                }
            }
        }
        __syncthreads();

        // ---- compute 4 k-steps of 8 ----
        #pragma unroll
        for (int ks = 0; ks < 4; ++ks) {
            int kc = ks * 8 + (lane & 3);
            uint32_t af[MT][4], bf[NTL][2];
            #pragma unroll
            for (int mt = 0; mt < MT; ++mt) {
                int mr = wm * WM + mt * 16 + (lane >> 2);
                af[mt][0] = As[mr * ASTR + kc];
                af[mt][1] = As[(mr + 8) * ASTR + kc];
                af[mt][2] = As[mr * ASTR + kc + 4];
                af[mt][3] = As[(mr + 8) * ASTR + kc + 4];
            }
            #pragma unroll
            for (int nt = 0; nt < NTL; ++nt) {
                int nc = wn * WN + nt * 8 + (lane >> 2);
                if (TB) {
                    bf[nt][0] = Bs[nc * 36 + kc];
                    bf[nt][1] = Bs[nc * 36 + kc + 4];
                } else {
                    bf[nt][0] = Bs[kc * (BN + 8) + nc];
                    bf[nt][1] = Bs[(kc + 4) * (BN + 8) + nc];
                }
            }
            #pragma unroll
            for (int mt = 0; mt < MT; ++mt)
                #pragma unroll
                for (int nt = 0; nt < NTL; ++nt)
                    mma_tf32(acc[mt][nt][0], acc[mt][nt][1], acc[mt][nt][2], acc[mt][nt][3],
                             af[mt][0], af[mt][1], af[mt][2], af[mt][3],
                             bf[nt][0], bf[nt][1]);
            if (SPLIT) {
                uint32_t al[MT][4];
                #pragma unroll
                for (int mt = 0; mt < MT; ++mt) {
                    int mr = wm * WM + mt * 16 + (lane >> 2);
                    al[mt][0] = As[ASZ + mr * ASTR + kc];
                    al[mt][1] = As[ASZ + (mr + 8) * ASTR + kc];
                    al[mt][2] = As[ASZ + mr * ASTR + kc + 4];
                    al[mt][3] = As[ASZ + (mr + 8) * ASTR + kc + 4];
                }
                #pragma unroll
                for (int mt = 0; mt < MT; ++mt)
                    #pragma unroll
                    for (int nt = 0; nt < NTL; ++nt)
                        mma_tf32(acc[mt][nt][0], acc[mt][nt][1], acc[mt][nt][2], acc[mt][nt][3],
                                 al[mt][0], al[mt][1], al[mt][2], al[mt][3],
                                 bf[nt][0], bf[nt][1]);
                uint32_t bl[NTL][2];
                #pragma unroll
                for (int nt = 0; nt < NTL; ++nt) {
                    int nc = wn * WN + nt * 8 + (lane >> 2);
                    if (TB) {
                        bl[nt][0] = Bs[BSZ + nc * 36 + kc];
                        bl[nt][1] = Bs[BSZ + nc * 36 + kc + 4];
                    } else {
                        bl[nt][0] = Bs[BSZ + kc * (BN + 8) + nc];
                        bl[nt][1] = Bs[BSZ + (kc + 4) * (BN + 8) + nc];
                    }
                }
                #pragma unroll
                for (int mt = 0; mt < MT; ++mt)
                    #pragma unroll
                    for (int nt = 0; nt < NTL; ++nt)
                        mma_tf32(acc[mt][nt][0], acc[mt][nt][1], acc[mt][nt][2], acc[mt][nt][3],
                                 af[mt][0], af[mt][1], af[mt][2], af[mt][3],
                                 bl[nt][0], bl[nt][1]);
            }
        }
    }

    // ---- epilogue ----
    #pragma unroll
    for (int mt = 0; mt < MT; ++mt) {
        int mr = row0 + wm * WM + mt * 16 + (lane >> 2);
        #pragma unroll
        for (int nt = 0; nt < NTL; ++nt) {
            int nc = col0 + wn * WN + nt * 8 + 2 * (lane & 3);
            float b0 = 0.f, b1 = 0.f;
            if (HAS_BIAS) { b0 = bias[nc]; b1 = bias[nc + 1]; }
            float2 v0 = make_float2(acc[mt][nt][0] * alpha + b0, acc[mt][nt][1] * alpha + b1);
            float2 v1 = make_float2(acc[mt][nt][2] * alpha + b0, acc[mt][nt][3] * alpha + b1);
            *(float2*)(C + (size_t)mr * ldc + nc) = v0;
            *(float2*)(C + (size_t)(mr + 8) * ldc + nc) = v1;
        }
    }
}

// ---------------------------------------------------------------------------
// Row L2-normalize: y = x / ||x||  (one block per row, D = 768, 256 threads)
// ---------------------------------------------------------------------------
__global__ __launch_bounds__(256) void rownorm_kernel(
    const float* __restrict__ x, float* __restrict__ y) {
    __shared__ float sh[256];
    size_t row = blockIdx.x;
    int tid = threadIdx.x;
    const float* xr = x + row * D;
    float* yr = y + row * D;
    float v0 = xr[tid], v1 = xr[tid + 256], v2 = xr[tid + 512];
    float ss = blockReduceSum(v0 * v0 + v1 * v1 + v2 * v2, sh);
    float inv = rsqrtf(ss);
    yr[tid] = v0 * inv; yr[tid + 256] = v1 * inv; yr[tid + 512] = v2 * inv;
}

// ---------------------------------------------------------------------------
// Top-8 per row of sim. jax.lax.top_k semantics: sorted desc, ties -> lower idx.
// ---------------------------------------------------------------------------
__global__ __launch_bounds__(256) void topk_kernel(
    const float* __restrict__ sim, int* __restrict__ out) {
    __shared__ float sv[256][KP];
    __shared__ int   si[256][KP];
    int row = blockIdx.x;
    int tid = threadIdx.x;
    const float* s = sim + (size_t)row * NDICT;
    float tv[KP]; int ti[KP];
    #pragma unroll
    for (int i = 0; i < KP; ++i) { tv[i] = -3.4e38f; ti[i] = 0x7fffffff; }
    for (int j4 = tid; j4 < NDICT / 4; j4 += 256) {
        float4 v4 = *(const float4*)(s + (size_t)j4 * 4);
        float vv[4] = {v4.x, v4.y, v4.z, v4.w};
        #pragma unroll
        for (int c = 0; c < 4; ++c) {
            float v = vv[c];
            if (v > tv[KP - 1]) {
                int j = j4 * 4 + c;
                int p = KP - 1;
                while (p > 0 && v > tv[p - 1]) { tv[p] = tv[p - 1]; ti[p] = ti[p - 1]; --p; }
                tv[p] = v; ti[p] = j;
            }
        }
    }
    #pragma unroll
    for (int i = 0; i < KP; ++i) { sv[tid][i] = tv[i]; si[tid][i] = ti[i]; }
    __syncthreads();
    for (int st = 128; st >= 1; st >>= 1) {
        if (tid < st) {
            float mv[KP]; int mi[KP]; int pa = 0, pb = 0;
            #pragma unroll
            for (int o = 0; o < KP; ++o) {
                float va = sv[tid][pa], vb = sv[tid + st][pb];
                int ia = si[tid][pa], ib = si[tid + st][pb];
                bool takeA = (va > vb) || (va == vb && ia <= ib);
                if (takeA) { mv[o] = va; mi[o] = ia; ++pa; }
                else       { mv[o] = vb; mi[o] = ib; ++pb; }
            }
            #pragma unroll
            for (int o = 0; o < KP; ++o) { sv[tid][o] = mv[o]; si[tid][o] = mi[o]; }
        }
        __syncthreads();
    }
    if (tid < KP) out[(size_t)row * KP + tid] = si[0][tid];
}

// ---------------------------------------------------------------------------
// Gather retrieved prototypes (UNnormalized dict rows) into [B*SKG, D]
// ---------------------------------------------------------------------------
__global__ __launch_bounds__(256) void gather_kernel(
    const float* __restrict__ dict, const int* __restrict__ topk,
    float* __restrict__ gfeats) {
    int r = blockIdx.x;
    int b = r >> 11;
    int pos = r & 2047;
    int idx = topk[((size_t)(b * L + (pos >> 3))) * KP + (pos & 7)];
    const float* src = dict + (size_t)idx * D;
    float* dst = gfeats + (size_t)r * D;
    for (int j = threadIdx.x; j < D; j += 256) dst[j] = src[j];
}

// ---------------------------------------------------------------------------
// Row softmax in-place over rows of length Sk (256 or 2048)
// ---------------------------------------------------------------------------
__global__ __launch_bounds__(256) void softmax_kernel(float* __restrict__ s, int Sk) {
    __shared__ float sh[256];
    size_t row = blockIdx.x;
    float* p = s + row * (size_t)Sk;
    int tid = threadIdx.x;
    int per = Sk >> 8;
    float vals[8];
    float m = -3.4e38f;
    for (int t = 0; t < per; ++t) { vals[t] = p[tid + (t << 8)]; m = fmaxf(m, vals[t]); }
    m = blockReduceMax(m, sh);
    float sum = 0.f;
    for (int t = 0; t < per; ++t) { vals[t] = expf(vals[t] - m); sum += vals[t]; }
    sum = blockReduceSum(sum, sh);
    float inv = 1.0f / sum;
    for (int t = 0; t < per; ++t) p[tid + (t << 8)] = vals[t] * inv;
}

// ---------------------------------------------------------------------------
// y = LayerNorm(x + residual) * g + beta
// ---------------------------------------------------------------------------
__global__ __launch_bounds__(256) void residual_ln_kernel(
    const float* __restrict__ x, const float* __restrict__ res,
    const float* __restrict__ g, const float* __restrict__ beta,
    float* __restrict__ out) {
    __shared__ float sh[256];
    size_t base = (size_t)blockIdx.x * D;
    int tid = threadIdx.x;
    float v[3];
    #pragma unroll
    for (int t = 0; t < 3; ++t) {
        int i = tid + (t << 8);
        v[t] = x[base + i] + res[base + i];
    }
    float mean = blockReduceSum(v[0] + v[1] + v[2], sh) * (1.0f / 768.0f);
    float d0 = v[0] - mean, d1 = v[1] - mean, d2 = v[2] - mean;
    float var = blockReduceSum(d0 * d0 + d1 * d1 + d2 * d2, sh) * (1.0f / 768.0f);
    float inv = rsqrtf(var + 1e-12f);
    #pragma unroll
    for (int t = 0; t < 3; ++t) {
        int i = tid + (t << 8);
        out[base + i] = (v[t] - mean) * inv * g[i] + beta[i];
    }
}

// ---------------------------------------------------------------------------
// Final: out_ln = LN(ll+lg); gate = sigmoid(out_ln.aug_w+aug_b+local.ori_w+ori_b)
//        result = gate*out_ln + (1-gate)*local
// ---------------------------------------------------------------------------
__global__ __launch_bounds__(256) void final_kernel(
    const float* __restrict__ ll, const float* __restrict__ lg,
    const float* __restrict__ local, const float* __restrict__ g,
    const float* __restrict__ beta, const float* __restrict__ aug_w,
    const float* __restrict__ aug_b, const float* __restrict__ ori_w,
    const float* __restrict__ ori_b, float* __restrict__ out) {
    __shared__ float sh[256];
    size_t base = (size_t)blockIdx.x * D;
    int tid = threadIdx.x;
    float s[3], lf[3];
    #pragma unroll
    for (int t = 0; t < 3; ++t) {
        int i = tid + (t << 8);
        s[t] = ll[base + i] + lg[base + i];
        lf[t] = local[base + i];
    }
    float mean = blockReduceSum(s[0] + s[1] + s[2], sh) * (1.0f / 768.0f);
    float d0 = s[0] - mean, d1 = s[1] - mean, d2 = s[2] - mean;
    float var = blockReduceSum(d0 * d0 + d1 * d1 + d2 * d2, sh) * (1.0f / 768.0f);
    float inv = rsqrtf(var + 1e-12f);
    float o[3];
    float dsum = 0.f;
    #pragma unroll
    for (int t = 0; t < 3; ++t) {
        int i = tid + (t << 8);
        o[t] = (s[t] - mean) * inv * g[i] + beta[i];
        dsum += o[t] * aug_w[i] + lf[t] * ori_w[i];
    }
    dsum = blockReduceSum(dsum, sh);
    float gate = 1.0f / (1.0f + expf(-(dsum + aug_b[0] + ori_b[0])));
    #pragma unroll
    for (int t = 0; t < 3; ++t) {
        int i = tid + (t << 8);
        out[base + i] = gate * o[t] + (1.0f - gate) * lf[t];
    }
}

// ---------------------------------------------------------------------------
// Host launcher
// ---------------------------------------------------------------------------
extern "C" void kernel_launch(void* const* d_in, const int* in_sizes, int n_in,
                              void* d_out, int out_size) {
    (void)n_in; (void)out_size;
    const float* local = (const float*)d_in[0];
    const float* dict  = (const float*)d_in[1];

    bool sig = (in_sizes[3] == 768);
    const float *W[2][4], *Bi[2][4], *LNG[2], *LNB[2];
    for (int p = 0; p < 2; ++p) {
        int base = 2 + p * 10;
        if (sig) {
            for (int j = 0; j < 4; ++j) {
                W[p][j]  = (const float*)d_in[base + 2 * j];
                Bi[p][j] = (const float*)d_in[base + 2 * j + 1];
            }
        } else {
            for (int j = 0; j < 4; ++j) {
                W[p][j]  = (const float*)d_in[base + j];
                Bi[p][j] = (const float*)d_in[base + 4 + j];
            }
        }
        LNG[p] = (const float*)d_in[base + 8];
        LNB[p] = (const float*)d_in[base + 9];
    }
    const float* ln_g = (const float*)d_in[22];
    const float* ln_b = (const float*)d_in[23];
    const float *aug_w, *aug_b, *ori_w, *ori_b;
    if (in_sizes[25] == 1) {
        aug_w = (const float*)d_in[24]; aug_b = (const float*)d_in[25];
        ori_w = (const float*)d_in[26]; ori_b = (const float*)d_in[27];
    } else {
        aug_w = (const float*)d_in[24]; ori_w = (const float*)d_in[25];
        aug_b = (const float*)d_in[26]; ori_b = (const float*)d_in[27];
    }

    float *p_tnorm, *p_gnorm, *p_sim, *p_gfeats, *p_q, *p_k, *p_v;
    float *p_scores, *p_ctx, *p_proj, *p_ll, *p_lg;
    int* p_topk;
    cudaGetSymbolAddress((void**)&p_tnorm, g_tnorm);
    cudaGetSymbolAddress((void**)&p_gnorm, g_gnorm);
    cudaGetSymbolAddress((void**)&p_sim, g_sim);
    cudaGetSymbolAddress((void**)&p_topk, g_topk);
    cudaGetSymbolAddress((void**)&p_gfeats, g_gfeats);
    cudaGetSymbolAddress((void**)&p_q, g_q);
    cudaGetSymbolAddress((void**)&p_k, g_k);
    cudaGetSymbolAddress((void**)&p_v, g_v);
    cudaGetSymbolAddress((void**)&p_scores, g_scores);
    cudaGetSymbolAddress((void**)&p_ctx, g_ctx);
    cudaGetSymbolAddress((void**)&p_proj, g_proj);
    cudaGetSymbolAddress((void**)&p_ll, g_ll);
    cudaGetSymbolAddress((void**)&p_lg, g_lg);

    // dynamic smem sizes (uint32 words * 4)
    const int SM_SIM   = 2 * (128 * 36 + 128 * 36) * 4;   // 73728 (split NT)
    const int SM_NN    = (128 * 36 + 32 * 136) * 4;       // 35840
    const int SM_NT    = (128 * 36 + 128 * 36) * 4;       // 36864
    const int SM_CTX   = (128 * 36 + 32 * 72) * 4;        // 27648

    cudaFuncSetAttribute(tf32gemm<128, 128, true, true, false>,
                         cudaFuncAttributeMaxDynamicSharedMemorySize, SM_SIM);

    // 1) normalize
    rownorm_kernel<<<NDICT, 256>>>(dict, p_gnorm);
    rownorm_kernel<<<M, 256>>>(local, p_tnorm);

    // 2) sim = tnorm @ gnorm^T  [2048 x 16384] in 3xTF32 (top-k safe)
    tf32gemm<128, 128, true, true, false>
        <<<dim3(NDICT / 128, M / 128, 1), 256, SM_SIM>>>(
        p_tnorm, p_gnorm, nullptr, p_sim, D, D, D, NDICT,
        0, 0, 0, 0, 0, 0, 1.0f);

    // 3) top-8 per row, 4) gather prototypes
    topk_kernel<<<M, 256>>>(p_sim, p_topk);
    gather_kernel<<<B * SKG, 256>>>(dict, p_topk, p_gfeats);

    dim3 gProj(D / 128, M / 128, 1);              // (6,16)
    dim3 gProjBig(D / 128, (B * SKG) / 128, 1);   // (6,128)

    // ---- ll: self-attention over locals ----
    tf32gemm<128, 128, false, false, true><<<gProj, 256, SM_NN>>>(
        local, W[0][0], Bi[0][0], p_q, D, D, D, D, 0, 0, 0, 0, 0, 0, 1.0f);
    tf32gemm<128, 128, false, false, true><<<gProj, 256, SM_NN>>>(
        local, W[0][1], Bi[0][1], p_k, D, D, D, D, 0, 0, 0, 0, 0, 0, 1.0f);
    tf32gemm<128, 128, false, false, true><<<gProj, 256, SM_NN>>>(
        local, W[0][2], Bi[0][2], p_v, D, D, D, D, 0, 0, 0, 0, 0, 0, 1.0f);
    // scores: [256 x 256] per (b,h), NT, K=64, alpha=1/8
    tf32gemm<128, 128, true, false, false>
        <<<dim3(L / 128, L / 128, BH), 256, SM_NT>>>(
        p_q, p_k, nullptr, p_scores, DH, D, D, L,
        (long)L * D, DH, (long)L * D, DH, (long)H * L * L, (long)L * L, 0.125f);
    softmax_kernel<<<BH * L, 256>>>(p_scores, L);
    // ctx: [256 x 64] per (b,h), NN, K=256
    tf32gemm<128, 64, false, false, false>
        <<<dim3(1, L / 128, BH), 256, SM_CTX>>>(
        p_scores, p_v, nullptr, p_ctx, L, L, D, D,
        (long)H * L * L, (long)L * L, (long)L * D, DH, (long)L * D, DH, 1.0f);
    tf32gemm<128, 128, false, false, true><<<gProj, 256, SM_NN>>>(
        p_ctx, W[0][3], Bi[0][3], p_proj, D, D, D, D, 0, 0, 0, 0, 0, 0, 1.0f);
    residual_ln_kernel<<<M, 256>>>(p_proj, local, LNG[0], LNB[0], p_ll);

    // ---- lg: cross-attention to retrieved prototypes ----
    tf32gemm<128, 128, false, false, true><<<gProj, 256, SM_NN>>>(
        local, W[1][0], Bi[1][0], p_q, D, D, D, D, 0, 0, 0, 0, 0, 0, 1.0f);
    tf32gemm<128, 128, false, false, true><<<gProjBig, 256, SM_NN>>>(
        p_gfeats, W[1][1], Bi[1][1], p_k, D, D, D, D, 0, 0, 0, 0, 0, 0, 1.0f);
    tf32gemm<128, 128, false, false, true><<<gProjBig, 256, SM_NN>>>(
        p_gfeats, W[1][2], Bi[1][2], p_v, D, D, D, D, 0, 0, 0, 0, 0, 0, 1.0f);
    // scores: [256 x 2048] per (b,h), NT, K=64
    tf32gemm<128, 128, true, false, false>
        <<<dim3(SKG / 128, L / 128, BH), 256, SM_NT>>>(
        p_q, p_k, nullptr, p_scores, DH, D, D, SKG,
        (long)L * D, DH, (long)SKG * D, DH, (long)H * L * SKG, (long)L * SKG, 0.125f);
    softmax_kernel<<<BH * L, 256>>>(p_scores, SKG);
    // ctx: [256 x 64] per (b,h), NN, K=2048
    tf32gemm<128, 64, false, false, false>
        <<<dim3(1, L / 128, BH), 256, SM_CTX>>>(
        p_scores, p_v, nullptr, p_ctx, SKG, SKG, D, D,
        (long)H * L * SKG, (long)L * SKG, (long)SKG * D, DH, (long)L * D, DH, 1.0f);
    tf32gemm<128, 128, false, false, true><<<gProj, 256, SM_NN>>>(
        p_ctx, W[1][3], Bi[1][3], p_proj, D, D, D, D, 0, 0, 0, 0, 0, 0, 1.0f);
    residual_ln_kernel<<<M, 256>>>(p_proj, local, LNG[1], LNB[1], p_lg);

    // ---- final LN + gating ----
    final_kernel<<<M, 256>>>(p_ll, p_lg, local, ln_g, ln_b,
                             aug_w, aug_b, ori_w, ori_b, (float*)d_out);
}

// round 8
// speedup vs baseline: 2.3060x; 1.1251x over previous
#include <cuda_runtime.h>
#include <cstdint>

// ---------------------------------------------------------------------------
// Problem constants
// ---------------------------------------------------------------------------
constexpr int B     = 8;
constexpr int L     = 256;
constexpr int D     = 768;
constexpr int H     = 12;
constexpr int DH    = 64;          // D / H
constexpr int M     = B * L;       // 2048 total query rows
constexpr int NDICT = 16384;
constexpr int KP    = 8;           // top-k
constexpr int SKG   = L * KP;      // 2048 kv rows per batch (cross-attn)
constexpr int BH    = B * H;       // 96

// ---------------------------------------------------------------------------
// Device-global scratch (no dynamic allocation allowed)
// ---------------------------------------------------------------------------
__device__ __align__(16) float g_tnorm[(size_t)M * D];
__device__ __align__(16) float g_gnorm[(size_t)NDICT * D];
__device__ __align__(16) float g_sim[(size_t)M * NDICT];
__device__ int   g_topk[(size_t)M * KP];
__device__ __align__(16) float g_gfeats[(size_t)B * SKG * D];
__device__ __align__(16) float g_q[(size_t)M * D];
__device__ __align__(16) float g_k[(size_t)B * SKG * D];
__device__ __align__(16) float g_v[(size_t)B * SKG * D];
__device__ __align__(16) float g_scores[(size_t)BH * L * SKG];
__device__ __align__(16) float g_ctx[(size_t)M * D];
__device__ __align__(16) float g_proj[(size_t)M * D];
__device__ __align__(16) float g_ll[(size_t)M * D];
__device__ __align__(16) float g_lg[(size_t)M * D];

#define DEV_INLINE __device__ __forceinline__

DEV_INLINE float blockReduceSum(float v, float* sh) {
    int tid = threadIdx.x;
    sh[tid] = v; __syncthreads();
    #pragma unroll
    for (int s = 128; s > 0; s >>= 1) {
        if (tid < s) sh[tid] += sh[tid + s];
        __syncthreads();
    }
    float r = sh[0]; __syncthreads();
    return r;
}

DEV_INLINE float blockReduceMax(float v, float* sh) {
    int tid = threadIdx.x;
    sh[tid] = v; __syncthreads();
    #pragma unroll
    for (int s = 128; s > 0; s >>= 1) {
        if (tid < s) sh[tid] = fmaxf(sh[tid], sh[tid + s]);
        __syncthreads();
    }
    float r = sh[0]; __syncthreads();
    return r;
}

// ---------------------------------------------------------------------------
// mma + cp.async helpers
// ---------------------------------------------------------------------------
DEV_INLINE void mma_tf32(float& c0, float& c1, float& c2, float& c3,
                         uint32_t a0, uint32_t a1, uint32_t a2, uint32_t a3,
                         uint32_t b0, uint32_t b1) {
    asm volatile(
        "mma.sync.aligned.m16n8k8.row.col.f32.tf32.tf32.f32 "
        "{%0,%1,%2,%3}, {%4,%5,%6,%7}, {%8,%9}, {%0,%1,%2,%3};"
        : "+f"(c0), "+f"(c1), "+f"(c2), "+f"(c3)
        : "r"(a0), "r"(a1), "r"(a2), "r"(a3), "r"(b0), "r"(b1));
}

DEV_INLINE void cpasync16(uint32_t dst_smem_bytes, const void* src) {
    asm volatile("cp.async.cg.shared.global [%0], [%1], 16;\n"
                 :: "r"(dst_smem_bytes), "l"(src));
}
DEV_INLINE void cp_commit() { asm volatile("cp.async.commit_group;\n" ::); }
DEV_INLINE void cp_wait1()  { asm volatile("cp.async.wait_group 1;\n" ::); }

// ---------------------------------------------------------------------------
// tf32 tensor-core GEMM, 2-stage cp.async pipeline, raw-f32 smem.
//   C[m,n] = alpha * A[m,:] . op(B)[:,n]  (+ bias[n])
//   TB=true : B is [N,K] row-major (NT)    TB=false: B is [K,N] row-major (NN)
//   SPLIT=true: 3xTF32 via on-the-fly truncation split (~fp32 accuracy)
// Batched over blockIdx.z: operand offset = (z/H)*SB + (z%H)*SH per operand.
// BM = 128, BN in {128, 64}. BK = 32. 256 threads (8 warps).
// Dynamic smem: 2 * (ASZ + BSZ) * 4 bytes.
// ---------------------------------------------------------------------------
template <int BM, int BN, bool TB, bool SPLIT, bool HAS_BIAS>
__global__ __launch_bounds__(256) void tf32gemm(
    const float* __restrict__ Ag, const float* __restrict__ Bg,
    const float* __restrict__ bias, float* __restrict__ Cg,
    int Kdim, int lda, int ldb, int ldc,
    long aSB, long aSH, long bSB, long bSH, long cSB, long cSH,
    float alpha) {
    constexpr int BK = 32;
    constexpr int WN_CNT = (BN == 128) ? 4 : 2;
    constexpr int WM = BM / (8 / WN_CNT);   // 64 or 32
    constexpr int WN = BN / WN_CNT;         // 32
    constexpr int MT = WM / 16;             // 4 or 2
    constexpr int NTL = WN / 8;             // 4
    constexpr int ASTR = 36;                       // [m][k] stride (words)
    constexpr int ASZ = BM * ASTR;
    constexpr int BSZ = TB ? (BN * 36) : (BK * (BN + 8));
    constexpr int STG = ASZ + BSZ;

    extern __shared__ uint32_t dynsmem[];
    uint32_t smem0 = (uint32_t)__cvta_generic_to_shared(dynsmem);

    int tid = threadIdx.x;
    int lane = tid & 31, warp = tid >> 5;
    int wm = warp / WN_CNT, wn = warp % WN_CNT;
    int row0 = blockIdx.y * BM;
    int col0 = blockIdx.x * BN;
    int z = blockIdx.z;
    int zb = z / H, zh = z % H;

    const float* A = Ag + (size_t)zb * aSB + (size_t)zh * aSH;
    const float* Bp = Bg + (size_t)zb * bSB + (size_t)zh * bSH;
    float* C = Cg + (size_t)zb * cSB + (size_t)zh * cSH;

    float acc[MT][NTL][4];
    #pragma unroll
    for (int i = 0; i < MT; ++i)
        #pragma unroll
        for (int j = 0; j < NTL; ++j)
            #pragma unroll
            for (int c = 0; c < 4; ++c) acc[i][j][c] = 0.f;

    int aK = tid & 7;       // float4 index along k (A / NT-B copies)
    int aM = tid >> 3;      // 0..31
    constexpr int BV = BN / 4;
    int bN = tid % BV;
    int bK = tid / BV;
    constexpr int BKSTEP = 256 / BV;

    auto issue_copy = [&](int k0, int s) {
        uint32_t abase = smem0 + (uint32_t)(s * STG) * 4u;
        #pragma unroll
        for (int mm = 0; mm < BM; mm += 32) {
            int r = mm + aM;
            cpasync16(abase + (uint32_t)(r * ASTR + aK * 4) * 4u,
                      A + (size_t)(row0 + r) * lda + k0 + aK * 4);
        }
        uint32_t bbase = abase + (uint32_t)ASZ * 4u;
        if (TB) {
            #pragma unroll
            for (int nn = 0; nn < BN; nn += 32) {
                int r = nn + aM;
                cpasync16(bbase + (uint32_t)(r * 36 + aK * 4) * 4u,
                          Bp + (size_t)(col0 + r) * ldb + k0 + aK * 4);
            }
        } else {
            #pragma unroll
            for (int kk = 0; kk < BK; kk += BKSTEP) {
                int r = kk + bK;
                cpasync16(bbase + (uint32_t)(r * (BN + 8) + bN * 4) * 4u,
                          Bp + (size_t)(k0 + r) * ldb + col0 + bN * 4);
            }
        }
    };

    issue_copy(0, 0);
    cp_commit();

    int nIter = Kdim / BK;
    for (int it = 0; it < nIter; ++it) {
        if (it + 1 < nIter) issue_copy((it + 1) * BK, (it + 1) & 1);
        cp_commit();
        cp_wait1();
        __syncthreads();

        const uint32_t* As = dynsmem + (it & 1) * STG;
        const uint32_t* Bs = As + ASZ;

        #pragma unroll
        for (int ks = 0; ks < 4; ++ks) {
            int kc = ks * 8 + (lane & 3);
            uint32_t af[MT][4], bf[NTL][2];
            #pragma unroll
            for (int mt = 0; mt < MT; ++mt) {
                int mr = wm * WM + mt * 16 + (lane >> 2);
                af[mt][0] = As[mr * ASTR + kc];
                af[mt][1] = As[(mr + 8) * ASTR + kc];
                af[mt][2] = As[mr * ASTR + kc + 4];
                af[mt][3] = As[(mr + 8) * ASTR + kc + 4];
            }
            #pragma unroll
            for (int nt = 0; nt < NTL; ++nt) {
                int nc = wn * WN + nt * 8 + (lane >> 2);
                if (TB) {
                    bf[nt][0] = Bs[nc * 36 + kc];
                    bf[nt][1] = Bs[nc * 36 + kc + 4];
                } else {
                    bf[nt][0] = Bs[kc * (BN + 8) + nc];
                    bf[nt][1] = Bs[(kc + 4) * (BN + 8) + nc];
                }
            }
            if (!SPLIT) {
                #pragma unroll
                for (int mt = 0; mt < MT; ++mt)
                    #pragma unroll
                    for (int nt = 0; nt < NTL; ++nt)
                        mma_tf32(acc[mt][nt][0], acc[mt][nt][1],
                                 acc[mt][nt][2], acc[mt][nt][3],
                                 af[mt][0], af[mt][1], af[mt][2], af[mt][3],
                                 bf[nt][0], bf[nt][1]);
            } else {
                // truncation split: hi = bits & ~0x1FFF (== HW-used part), lo = x - hi
                uint32_t al[MT][4], bl[NTL][2];
                #pragma unroll
                for (int mt = 0; mt < MT; ++mt)
                    #pragma unroll
                    for (int c = 0; c < 4; ++c) {
                        uint32_t h = af[mt][c] & 0xFFFFE000u;
                        al[mt][c] = __float_as_uint(
                            __uint_as_float(af[mt][c]) - __uint_as_float(h));
                        af[mt][c] = h;
                    }
                #pragma unroll
                for (int nt = 0; nt < NTL; ++nt)
                    #pragma unroll
                    for (int c = 0; c < 2; ++c) {
                        uint32_t h = bf[nt][c] & 0xFFFFE000u;
                        bl[nt][c] = __float_as_uint(
                            __uint_as_float(bf[nt][c]) - __uint_as_float(h));
                        bf[nt][c] = h;
                    }
                #pragma unroll
                for (int mt = 0; mt < MT; ++mt)
                    #pragma unroll
                    for (int nt = 0; nt < NTL; ++nt) {
                        mma_tf32(acc[mt][nt][0], acc[mt][nt][1],
                                 acc[mt][nt][2], acc[mt][nt][3],
                                 af[mt][0], af[mt][1], af[mt][2], af[mt][3],
                                 bf[nt][0], bf[nt][1]);
                        mma_tf32(acc[mt][nt][0], acc[mt][nt][1],
                                 acc[mt][nt][2], acc[mt][nt][3],
                                 al[mt][0], al[mt][1], al[mt][2], al[mt][3],
                                 bf[nt][0], bf[nt][1]);
                        mma_tf32(acc[mt][nt][0], acc[mt][nt][1],
                                 acc[mt][nt][2], acc[mt][nt][3],
                                 af[mt][0], af[mt][1], af[mt][2], af[mt][3],
                                 bl[nt][0], bl[nt][1]);
                    }
            }
        }
        __syncthreads();
    }

    // ---- epilogue ----
    #pragma unroll
    for (int mt = 0; mt < MT; ++mt) {
        int mr = row0 + wm * WM + mt * 16 + (lane >> 2);
        #pragma unroll
        for (int nt = 0; nt < NTL; ++nt) {
            int nc = col0 + wn * WN + nt * 8 + 2 * (lane & 3);
            float b0 = 0.f, b1 = 0.f;
            if (HAS_BIAS) { b0 = bias[nc]; b1 = bias[nc + 1]; }
            float2 v0 = make_float2(acc[mt][nt][0] * alpha + b0,
                                    acc[mt][nt][1] * alpha + b1);
            float2 v1 = make_float2(acc[mt][nt][2] * alpha + b0,
                                    acc[mt][nt][3] * alpha + b1);
            *(float2*)(C + (size_t)mr * ldc + nc) = v0;
            *(float2*)(C + (size_t)(mr + 8) * ldc + nc) = v1;
        }
    }
}

// ---------------------------------------------------------------------------
// Row L2-normalize: y = x / ||x||  (one block per row, D = 768, 256 threads)
// ---------------------------------------------------------------------------
__global__ __launch_bounds__(256) void rownorm_kernel(
    const float* __restrict__ x, float* __restrict__ y) {
    __shared__ float sh[256];
    size_t row = blockIdx.x;
    int tid = threadIdx.x;
    const float* xr = x + row * D;
    float* yr = y + row * D;
    float v0 = xr[tid], v1 = xr[tid + 256], v2 = xr[tid + 512];
    float ss = blockReduceSum(v0 * v0 + v1 * v1 + v2 * v2, sh);
    float inv = rsqrtf(ss);
    yr[tid] = v0 * inv; yr[tid + 256] = v1 * inv; yr[tid + 512] = v2 * inv;
}

// ---------------------------------------------------------------------------
// Top-8 per row of sim. jax.lax.top_k semantics: sorted desc, ties -> lower idx.
// ---------------------------------------------------------------------------
__global__ __launch_bounds__(256) void topk_kernel(
    const float* __restrict__ sim, int* __restrict__ out) {
    __shared__ float sv[256][KP];
    __shared__ int   si[256][KP];
    int row = blockIdx.x;
    int tid = threadIdx.x;
    const float* s = sim + (size_t)row * NDICT;
    float tv[KP]; int ti[KP];
    #pragma unroll
    for (int i = 0; i < KP; ++i) { tv[i] = -3.4e38f; ti[i] = 0x7fffffff; }
    for (int j4 = tid; j4 < NDICT / 4; j4 += 256) {
        float4 v4 = *(const float4*)(s + (size_t)j4 * 4);
        float vv[4] = {v4.x, v4.y, v4.z, v4.w};
        #pragma unroll
        for (int c = 0; c < 4; ++c) {
            float v = vv[c];
            if (v > tv[KP - 1]) {
                int j = j4 * 4 + c;
                int p = KP - 1;
                while (p > 0 && v > tv[p - 1]) { tv[p] = tv[p - 1]; ti[p] = ti[p - 1]; --p; }
                tv[p] = v; ti[p] = j;
            }
        }
    }
    #pragma unroll
    for (int i = 0; i < KP; ++i) { sv[tid][i] = tv[i]; si[tid][i] = ti[i]; }
    __syncthreads();
    for (int st = 128; st >= 1; st >>= 1) {
        if (tid < st) {
            float mv[KP]; int mi[KP]; int pa = 0, pb = 0;
            #pragma unroll
            for (int o = 0; o < KP; ++o) {
                float va = sv[tid][pa], vb = sv[tid + st][pb];
                int ia = si[tid][pa], ib = si[tid + st][pb];
                bool takeA = (va > vb) || (va == vb && ia <= ib);
                if (takeA) { mv[o] = va; mi[o] = ia; ++pa; }
                else       { mv[o] = vb; mi[o] = ib; ++pb; }
            }
            #pragma unroll
            for (int o = 0; o < KP; ++o) { sv[tid][o] = mv[o]; si[tid][o] = mi[o]; }
        }
        __syncthreads();
    }
    if (tid < KP) out[(size_t)row * KP + tid] = si[0][tid];
}

// ---------------------------------------------------------------------------
// Gather retrieved prototypes (UNnormalized dict rows) into [B*SKG, D]
// ---------------------------------------------------------------------------
__global__ __launch_bounds__(256) void gather_kernel(
    const float* __restrict__ dict, const int* __restrict__ topk,
    float* __restrict__ gfeats) {
    int r = blockIdx.x;
    int b = r >> 11;
    int pos = r & 2047;
    int idx = topk[((size_t)(b * L + (pos >> 3))) * KP + (pos & 7)];
    const float* src = dict + (size_t)idx * D;
    float* dst = gfeats + (size_t)r * D;
    for (int j = threadIdx.x; j < D / 4; j += 256)
        ((float4*)dst)[j] = ((const float4*)src)[j];
}

// ---------------------------------------------------------------------------
// Row softmax in-place over rows of length Sk (256 or 2048)
// ---------------------------------------------------------------------------
__global__ __launch_bounds__(256) void softmax_kernel(float* __restrict__ s, int Sk) {
    __shared__ float sh[256];
    size_t row = blockIdx.x;
    float* p = s + row * (size_t)Sk;
    int tid = threadIdx.x;
    int per = Sk >> 8;
    float vals[8];
    float m = -3.4e38f;
    for (int t = 0; t < per; ++t) { vals[t] = p[tid + (t << 8)]; m = fmaxf(m, vals[t]); }
    m = blockReduceMax(m, sh);
    float sum = 0.f;
    for (int t = 0; t < per; ++t) { vals[t] = expf(vals[t] - m); sum += vals[t]; }
    sum = blockReduceSum(sum, sh);
    float inv = 1.0f / sum;
    for (int t = 0; t < per; ++t) p[tid + (t << 8)] = vals[t] * inv;
}

// ---------------------------------------------------------------------------
// y = LayerNorm(x + residual) * g + beta
// ---------------------------------------------------------------------------
__global__ __launch_bounds__(256) void residual_ln_kernel(
    const float* __restrict__ x, const float* __restrict__ res,
    const float* __restrict__ g, const float* __restrict__ beta,
    float* __restrict__ out) {
    __shared__ float sh[256];
    size_t base = (size_t)blockIdx.x * D;
    int tid = threadIdx.x;
    float v[3];
    #pragma unroll
    for (int t = 0; t < 3; ++t) {
        int i = tid + (t << 8);
        v[t] = x[base + i] + res[base + i];
    }
    float mean = blockReduceSum(v[0] + v[1] + v[2], sh) * (1.0f / 768.0f);
    float d0 = v[0] - mean, d1 = v[1] - mean, d2 = v[2] - mean;
    float var = blockReduceSum(d0 * d0 + d1 * d1 + d2 * d2, sh) * (1.0f / 768.0f);
    float inv = rsqrtf(var + 1e-12f);
    #pragma unroll
    for (int t = 0; t < 3; ++t) {
        int i = tid + (t << 8);
        out[base + i] = (v[t] - mean) * inv * g[i] + beta[i];
    }
}

// ---------------------------------------------------------------------------
// Final: out_ln = LN(ll+lg); gate = sigmoid(out_ln.aug_w+aug_b+local.ori_w+ori_b)
//        result = gate*out_ln + (1-gate)*local
// ---------------------------------------------------------------------------
__global__ __launch_bounds__(256) void final_kernel(
    const float* __restrict__ ll, const float* __restrict__ lg,
    const float* __restrict__ local, const float* __restrict__ g,
    const float* __restrict__ beta, const float* __restrict__ aug_w,
    const float* __restrict__ aug_b, const float* __restrict__ ori_w,
    const float* __restrict__ ori_b, float* __restrict__ out) {
    __shared__ float sh[256];
    size_t base = (size_t)blockIdx.x * D;
    int tid = threadIdx.x;
    float s[3], lf[3];
    #pragma unroll
    for (int t = 0; t < 3; ++t) {
        int i = tid + (t << 8);
        s[t] = ll[base + i] + lg[base + i];
        lf[t] = local[base + i];
    }
    float mean = blockReduceSum(s[0] + s[1] + s[2], sh) * (1.0f / 768.0f);
    float d0 = s[0] - mean, d1 = s[1] - mean, d2 = s[2] - mean;
    float var = blockReduceSum(d0 * d0 + d1 * d1 + d2 * d2, sh) * (1.0f / 768.0f);
    float inv = rsqrtf(var + 1e-12f);
    float o[3];
    float dsum = 0.f;
    #pragma unroll
    for (int t = 0; t < 3; ++t) {
        int i = tid + (t << 8);
        o[t] = (s[t] - mean) * inv * g[i] + beta[i];
        dsum += o[t] * aug_w[i] + lf[t] * ori_w[i];
    }
    dsum = blockReduceSum(dsum, sh);
    float gate = 1.0f / (1.0f + expf(-(dsum + aug_b[0] + ori_b[0])));
    #pragma unroll
    for (int t = 0; t < 3; ++t) {
        int i = tid + (t << 8);
        out[base + i] = gate * o[t] + (1.0f - gate) * lf[t];
    }
}

// ---------------------------------------------------------------------------
// Host launcher
// ---------------------------------------------------------------------------
extern "C" void kernel_launch(void* const* d_in, const int* in_sizes, int n_in,
                              void* d_out, int out_size) {
    (void)n_in; (void)out_size;
    const float* local = (const float*)d_in[0];
    const float* dict  = (const float*)d_in[1];

    bool sig = (in_sizes[3] == 768);
    const float *W[2][4], *Bi[2][4], *LNG[2], *LNB[2];
    for (int p = 0; p < 2; ++p) {
        int base = 2 + p * 10;
        if (sig) {
            for (int j = 0; j < 4; ++j) {
                W[p][j]  = (const float*)d_in[base + 2 * j];
                Bi[p][j] = (const float*)d_in[base + 2 * j + 1];
            }
        } else {
            for (int j = 0; j < 4; ++j) {
                W[p][j]  = (const float*)d_in[base + j];
                Bi[p][j] = (const float*)d_in[base + 4 + j];
            }
        }
        LNG[p] = (const float*)d_in[base + 8];
        LNB[p] = (const float*)d_in[base + 9];
    }
    const float* ln_g = (const float*)d_in[22];
    const float* ln_b = (const float*)d_in[23];
    const float *aug_w, *aug_b, *ori_w, *ori_b;
    if (in_sizes[25] == 1) {
        aug_w = (const float*)d_in[24]; aug_b = (const float*)d_in[25];
        ori_w = (const float*)d_in[26]; ori_b = (const float*)d_in[27];
    } else {
        aug_w = (const float*)d_in[24]; ori_w = (const float*)d_in[25];
        aug_b = (const float*)d_in[26]; ori_b = (const float*)d_in[27];
    }

    float *p_tnorm, *p_gnorm, *p_sim, *p_gfeats, *p_q, *p_k, *p_v;
    float *p_scores, *p_ctx, *p_proj, *p_ll, *p_lg;
    int* p_topk;
    cudaGetSymbolAddress((void**)&p_tnorm, g_tnorm);
    cudaGetSymbolAddress((void**)&p_gnorm, g_gnorm);
    cudaGetSymbolAddress((void**)&p_sim, g_sim);
    cudaGetSymbolAddress((void**)&p_topk, g_topk);
    cudaGetSymbolAddress((void**)&p_gfeats, g_gfeats);
    cudaGetSymbolAddress((void**)&p_q, g_q);
    cudaGetSymbolAddress((void**)&p_k, g_k);
    cudaGetSymbolAddress((void**)&p_v, g_v);
    cudaGetSymbolAddress((void**)&p_scores, g_scores);
    cudaGetSymbolAddress((void**)&p_ctx, g_ctx);
    cudaGetSymbolAddress((void**)&p_proj, g_proj);
    cudaGetSymbolAddress((void**)&p_ll, g_ll);
    cudaGetSymbolAddress((void**)&p_lg, g_lg);

    // dynamic smem: 2 stages * (ASZ + BSZ) words * 4 bytes
    const int SM_NT  = 2 * (128 * 36 + 128 * 36) * 4;  // 73728 (sim + scores)
    const int SM_NN  = 2 * (128 * 36 + 32 * 136) * 4;  // 71680 (projections)
    const int SM_CTX = 2 * (128 * 36 + 32 * 72) * 4;   // 55296 (ctx, BN=64)

    cudaFuncSetAttribute(tf32gemm<128, 128, true, true, false>,
                         cudaFuncAttributeMaxDynamicSharedMemorySize, SM_NT);
    cudaFuncSetAttribute(tf32gemm<128, 128, true, false, false>,
                         cudaFuncAttributeMaxDynamicSharedMemorySize, SM_NT);
    cudaFuncSetAttribute(tf32gemm<128, 128, false, false, true>,
                         cudaFuncAttributeMaxDynamicSharedMemorySize, SM_NN);
    cudaFuncSetAttribute(tf32gemm<128, 64, false, false, false>,
                         cudaFuncAttributeMaxDynamicSharedMemorySize, SM_CTX);

    // 1) normalize
    rownorm_kernel<<<NDICT, 256>>>(dict, p_gnorm);
    rownorm_kernel<<<M, 256>>>(local, p_tnorm);

    // 2) sim = tnorm @ gnorm^T  [2048 x 16384] in 3xTF32 (top-k safe)
    tf32gemm<128, 128, true, true, false>
        <<<dim3(NDICT / 128, M / 128, 1), 256, SM_NT>>>(
        p_tnorm, p_gnorm, nullptr, p_sim, D, D, D, NDICT,
        0, 0, 0, 0, 0, 0, 1.0f);

    // 3) top-8 per row, 4) gather prototypes
    topk_kernel<<<M, 256>>>(p_sim, p_topk);
    gather_kernel<<<B * SKG, 256>>>(dict, p_topk, p_gfeats);

    dim3 gProj(D / 128, M / 128, 1);              // (6,16)
    dim3 gProjBig(D / 128, (B * SKG) / 128, 1);   // (6,128)

    // ---- ll: self-attention over locals ----
    tf32gemm<128, 128, false, false, true><<<gProj, 256, SM_NN>>>(
        local, W[0][0], Bi[0][0], p_q, D, D, D, D, 0, 0, 0, 0, 0, 0, 1.0f);
    tf32gemm<128, 128, false, false, true><<<gProj, 256, SM_NN>>>(
        local, W[0][1], Bi[0][1], p_k, D, D, D, D, 0, 0, 0, 0, 0, 0, 1.0f);
    tf32gemm<128, 128, false, false, true><<<gProj, 256, SM_NN>>>(
        local, W[0][2], Bi[0][2], p_v, D, D, D, D, 0, 0, 0, 0, 0, 0, 1.0f);
    // scores: [256 x 256] per (b,h), NT, K=64, alpha=1/8
    tf32gemm<128, 128, true, false, false>
        <<<dim3(L / 128, L / 128, BH), 256, SM_NT>>>(
        p_q, p_k, nullptr, p_scores, DH, D, D, L,
        (long)L * D, DH, (long)L * D, DH, (long)H * L * L, (long)L * L, 0.125f);
    softmax_kernel<<<BH * L, 256>>>(p_scores, L);
    // ctx: [256 x 64] per (b,h), NN, K=256
    tf32gemm<128, 64, false, false, false>
        <<<dim3(1, L / 128, BH), 256, SM_CTX>>>(
        p_scores, p_v, nullptr, p_ctx, L, L, D, D,
        (long)H * L * L, (long)L * L, (long)L * D, DH, (long)L * D, DH, 1.0f);
    tf32gemm<128, 128, false, false, true><<<gProj, 256, SM_NN>>>(
        p_ctx, W[0][3], Bi[0][3], p_proj, D, D, D, D, 0, 0, 0, 0, 0, 0, 1.0f);
    residual_ln_kernel<<<M, 256>>>(p_proj, local, LNG[0], LNB[0], p_ll);

    // ---- lg: cross-attention to retrieved prototypes ----
    tf32gemm<128, 128, false, false, true><<<gProj, 256, SM_NN>>>(
        local, W[1][0], Bi[1][0], p_q, D, D, D, D, 0, 0, 0, 0, 0, 0, 1.0f);
    tf32gemm<128, 128, false, false, true><<<gProjBig, 256, SM_NN>>>(
        p_gfeats, W[1][1], Bi[1][1], p_k, D, D, D, D, 0, 0, 0, 0, 0, 0, 1.0f);
    tf32gemm<128, 128, false, false, true><<<gProjBig, 256, SM_NN>>>(
        p_gfeats, W[1][2], Bi[1][2], p_v, D, D, D, D, 0, 0, 0, 0, 0, 0, 1.0f);
    // scores: [256 x 2048] per (b,h), NT, K=64
    tf32gemm<128, 128, true, false, false>
        <<<dim3(SKG / 128, L / 128, BH), 256, SM_NT>>>(
        p_q, p_k, nullptr, p_scores, DH, D, D, SKG,
        (long)L * D, DH, (long)SKG * D, DH, (long)H * L * SKG, (long)L * SKG, 0.125f);
    softmax_kernel<<<BH * L, 256>>>(p_scores, SKG);
    // ctx: [256 x 64] per (b,h), NN, K=2048
    tf32gemm<128, 64, false, false, false>
        <<<dim3(1, L / 128, BH), 256, SM_CTX>>>(
        p_scores, p_v, nullptr, p_ctx, SKG, SKG, D, D,
        (long)H * L * SKG, (long)L * SKG, (long)SKG * D, DH, (long)L * D, DH, 1.0f);
    tf32gemm<128, 128, false, false, true><<<gProj, 256, SM_NN>>>(
        p_ctx, W[1][3], Bi[1][3], p_proj, D, D, D, D, 0, 0, 0, 0, 0, 0, 1.0f);
    residual_ln_kernel<<<M, 256>>>(p_proj, local, LNG[1], LNB[1], p_lg);

    // ---- final LN + gating ----
    final_kernel<<<M, 256>>>(p_ll, p_lg, local, ln_g, ln_b,
                             aug_w, aug_b, ori_w, ori_b, (float*)d_out);
}

// round 9
// speedup vs baseline: 2.7711x; 1.2017x over previous
#include <cuda_runtime.h>
#include <cstdint>

// ---------------------------------------------------------------------------
// Problem constants
// ---------------------------------------------------------------------------
constexpr int B     = 8;
constexpr int L     = 256;
constexpr int D     = 768;
constexpr int H     = 12;
constexpr int DH    = 64;          // D / H
constexpr int M     = B * L;       // 2048 total query rows
constexpr int NDICT = 16384;
constexpr int KP    = 8;           // top-k
constexpr int SKG   = L * KP;      // 2048 kv rows per batch (cross-attn)
constexpr int BH    = B * H;       // 96

// ---------------------------------------------------------------------------
// Device-global scratch (no dynamic allocation allowed)
// ---------------------------------------------------------------------------
__device__ __align__(16) float g_tnorm[(size_t)M * D];
__device__ __align__(16) float g_gnorm[(size_t)NDICT * D];
__device__ __align__(16) float g_sim[(size_t)M * NDICT];
__device__ int   g_topk[(size_t)M * KP];
__device__ __align__(16) float g_gfeats[(size_t)B * SKG * D];
__device__ __align__(16) float g_q[(size_t)M * D];
__device__ __align__(16) float g_q2[(size_t)M * D];
__device__ __align__(16) float g_k[(size_t)B * SKG * D];
__device__ __align__(16) float g_v[(size_t)B * SKG * D];
__device__ __align__(16) float g_ctx[(size_t)M * D];
__device__ __align__(16) float g_ctx2[(size_t)M * D];
__device__ __align__(16) float g_proj[(size_t)M * D];
__device__ __align__(16) float g_proj2[(size_t)M * D];
__device__ __align__(16) float g_ll[(size_t)M * D];
__device__ __align__(16) float g_lg[(size_t)M * D];

#define DEV_INLINE __device__ __forceinline__

DEV_INLINE float blockReduceSum(float v, float* sh) {
    int tid = threadIdx.x;
    sh[tid] = v; __syncthreads();
    #pragma unroll
    for (int s = 128; s > 0; s >>= 1) {
        if (tid < s) sh[tid] += sh[tid + s];
        __syncthreads();
    }
    float r = sh[0]; __syncthreads();
    return r;
}

// ---------------------------------------------------------------------------
// mma + cp.async helpers
// ---------------------------------------------------------------------------
DEV_INLINE void mma_tf32(float& c0, float& c1, float& c2, float& c3,
                         uint32_t a0, uint32_t a1, uint32_t a2, uint32_t a3,
                         uint32_t b0, uint32_t b1) {
    asm volatile(
        "mma.sync.aligned.m16n8k8.row.col.f32.tf32.tf32.f32 "
        "{%0,%1,%2,%3}, {%4,%5,%6,%7}, {%8,%9}, {%0,%1,%2,%3};"
        : "+f"(c0), "+f"(c1), "+f"(c2), "+f"(c3)
        : "r"(a0), "r"(a1), "r"(a2), "r"(a3), "r"(b0), "r"(b1));
}

DEV_INLINE void cpasync16(uint32_t dst_smem_bytes, const void* src) {
    asm volatile("cp.async.cg.shared.global [%0], [%1], 16;\n"
                 :: "r"(dst_smem_bytes), "l"(src));
}
DEV_INLINE void cp_commit() { asm volatile("cp.async.commit_group;\n" ::); }
DEV_INLINE void cp_wait1()  { asm volatile("cp.async.wait_group 1;\n" ::); }
DEV_INLINE void cp_wait0()  { asm volatile("cp.async.wait_group 0;\n" ::); }

// ---------------------------------------------------------------------------
// tf32 GEMM (NT, 3xTF32 split) for the sim matrix. 2-stage cp.async pipeline.
//   C[m,n] = A[m,:] . B[n,:]   A:[M,K], B:[N,K] row-major. K mult of 32.
// BM=BN=128, BK=32, 256 threads.
// ---------------------------------------------------------------------------
__global__ __launch_bounds__(256) void tf32gemm_nt_split(
    const float* __restrict__ Ag, const float* __restrict__ Bg,
    float* __restrict__ Cg, int Kdim, int lda, int ldb, int ldc) {
    constexpr int BK = 32;
    constexpr int ASTR = 36;
    constexpr int ASZ = 128 * ASTR;
    constexpr int BSZ = 128 * 36;
    constexpr int STG = ASZ + BSZ;

    extern __shared__ uint32_t dynsmem[];
    uint32_t smem0 = (uint32_t)__cvta_generic_to_shared(dynsmem);

    int tid = threadIdx.x;
    int lane = tid & 31, warp = tid >> 5;
    int wm = warp >> 2, wn = warp & 3;       // 2x4 warps, WM=64, WN=32
    int row0 = blockIdx.y * 128;
    int col0 = blockIdx.x * 128;

    float acc[4][4][4];
    #pragma unroll
    for (int i = 0; i < 4; ++i)
        #pragma unroll
        for (int j = 0; j < 4; ++j)
            #pragma unroll
            for (int c = 0; c < 4; ++c) acc[i][j][c] = 0.f;

    int aK = tid & 7, aM = tid >> 3;

    auto issue_copy = [&](int k0, int s) {
        uint32_t abase = smem0 + (uint32_t)(s * STG) * 4u;
        #pragma unroll
        for (int mm = 0; mm < 128; mm += 32) {
            int r = mm + aM;
            cpasync16(abase + (uint32_t)(r * ASTR + aK * 4) * 4u,
                      Ag + (size_t)(row0 + r) * lda + k0 + aK * 4);
        }
        uint32_t bbase = abase + (uint32_t)ASZ * 4u;
        #pragma unroll
        for (int nn = 0; nn < 128; nn += 32) {
            int r = nn + aM;
            cpasync16(bbase + (uint32_t)(r * 36 + aK * 4) * 4u,
                      Bg + (size_t)(col0 + r) * ldb + k0 + aK * 4);
        }
    };

    issue_copy(0, 0);
    cp_commit();

    int nIter = Kdim / BK;
    for (int it = 0; it < nIter; ++it) {
        if (it + 1 < nIter) issue_copy((it + 1) * BK, (it + 1) & 1);
        cp_commit();
        cp_wait1();
        __syncthreads();

        const uint32_t* As = dynsmem + (it & 1) * STG;
        const uint32_t* Bs = As + ASZ;

        #pragma unroll
        for (int ks = 0; ks < 4; ++ks) {
            int kc = ks * 8 + (lane & 3);
            uint32_t af[4][4], bf[4][2];
            #pragma unroll
            for (int mt = 0; mt < 4; ++mt) {
                int mr = wm * 64 + mt * 16 + (lane >> 2);
                af[mt][0] = As[mr * ASTR + kc];
                af[mt][1] = As[(mr + 8) * ASTR + kc];
                af[mt][2] = As[mr * ASTR + kc + 4];
                af[mt][3] = As[(mr + 8) * ASTR + kc + 4];
            }
            #pragma unroll
            for (int nt = 0; nt < 4; ++nt) {
                int nc = wn * 32 + nt * 8 + (lane >> 2);
                bf[nt][0] = Bs[nc * 36 + kc];
                bf[nt][1] = Bs[nc * 36 + kc + 4];
            }
            uint32_t al[4][4], bl[4][2];
            #pragma unroll
            for (int mt = 0; mt < 4; ++mt)
                #pragma unroll
                for (int c = 0; c < 4; ++c) {
                    uint32_t h = af[mt][c] & 0xFFFFE000u;
                    al[mt][c] = __float_as_uint(
                        __uint_as_float(af[mt][c]) - __uint_as_float(h));
                    af[mt][c] = h;
                }
            #pragma unroll
            for (int nt = 0; nt < 4; ++nt)
                #pragma unroll
                for (int c = 0; c < 2; ++c) {
                    uint32_t h = bf[nt][c] & 0xFFFFE000u;
                    bl[nt][c] = __float_as_uint(
                        __uint_as_float(bf[nt][c]) - __uint_as_float(h));
                    bf[nt][c] = h;
                }
            #pragma unroll
            for (int mt = 0; mt < 4; ++mt)
                #pragma unroll
                for (int nt = 0; nt < 4; ++nt) {
                    mma_tf32(acc[mt][nt][0], acc[mt][nt][1],
                             acc[mt][nt][2], acc[mt][nt][3],
                             af[mt][0], af[mt][1], af[mt][2], af[mt][3],
                             bf[nt][0], bf[nt][1]);
                    mma_tf32(acc[mt][nt][0], acc[mt][nt][1],
                             acc[mt][nt][2], acc[mt][nt][3],
                             al[mt][0], al[mt][1], al[mt][2], al[mt][3],
                             bf[nt][0], bf[nt][1]);
                    mma_tf32(acc[mt][nt][0], acc[mt][nt][1],
                             acc[mt][nt][2], acc[mt][nt][3],
                             af[mt][0], af[mt][1], af[mt][2], af[mt][3],
                             bl[nt][0], bl[nt][1]);
                }
        }
        __syncthreads();
    }

    #pragma unroll
    for (int mt = 0; mt < 4; ++mt) {
        int mr = row0 + wm * 64 + mt * 16 + (lane >> 2);
        #pragma unroll
        for (int nt = 0; nt < 4; ++nt) {
            int nc = col0 + wn * 32 + nt * 8 + 2 * (lane & 3);
            *(float2*)(Cg + (size_t)mr * ldc + nc) =
                make_float2(acc[mt][nt][0], acc[mt][nt][1]);
            *(float2*)(Cg + (size_t)(mr + 8) * ldc + nc) =
                make_float2(acc[mt][nt][2], acc[mt][nt][3]);
        }
    }
}

// ---------------------------------------------------------------------------
// Multi-matrix NN projection GEMM: up to 4 (A, W, bias, C) sets per launch.
//   C[m,n] = A[m,:] @ W[:,n] + bias[n]   A:[rows,768], W:[768,768].
// sel = blockIdx.x / 6; col0 = (blockIdx.x % 6) * 128. BM=128,BN=128,BK=32.
// ---------------------------------------------------------------------------
struct Ptrs4 {
    const float* A[4];
    const float* W[4];
    const float* bias[4];
    float* C[4];
};

__global__ __launch_bounds__(256) void tf32gemm_nn_multi(Ptrs4 p) {
    constexpr int BK = 32;
    constexpr int ASTR = 36;
    constexpr int ASZ = 128 * ASTR;
    constexpr int BSZ = 32 * 136;
    constexpr int STG = ASZ + BSZ;

    extern __shared__ uint32_t dynsmem[];
    uint32_t smem0 = (uint32_t)__cvta_generic_to_shared(dynsmem);

    int sel = blockIdx.x / 6;
    int col0 = (blockIdx.x % 6) * 128;
    const float* A = p.A[sel];
    const float* Bp = p.W[sel];
    const float* bias = p.bias[sel];
    float* C = p.C[sel];

    int tid = threadIdx.x;
    int lane = tid & 31, warp = tid >> 5;
    int wm = warp >> 2, wn = warp & 3;
    int row0 = blockIdx.y * 128;

    float acc[4][4][4];
    #pragma unroll
    for (int i = 0; i < 4; ++i)
        #pragma unroll
        for (int j = 0; j < 4; ++j)
            #pragma unroll
            for (int c = 0; c < 4; ++c) acc[i][j][c] = 0.f;

    int aK = tid & 7, aM = tid >> 3;
    int bN = tid & 31, bK = tid >> 5;

    auto issue_copy = [&](int k0, int s) {
        uint32_t abase = smem0 + (uint32_t)(s * STG) * 4u;
        #pragma unroll
        for (int mm = 0; mm < 128; mm += 32) {
            int r = mm + aM;
            cpasync16(abase + (uint32_t)(r * ASTR + aK * 4) * 4u,
                      A + (size_t)(row0 + r) * D + k0 + aK * 4);
        }
        uint32_t bbase = abase + (uint32_t)ASZ * 4u;
        #pragma unroll
        for (int kk = 0; kk < 32; kk += 8) {
            int r = kk + bK;
            cpasync16(bbase + (uint32_t)(r * 136 + bN * 4) * 4u,
                      Bp + (size_t)(k0 + r) * D + col0 + bN * 4);
        }
    };

    issue_copy(0, 0);
    cp_commit();

    int nIter = D / BK;     // 24
    for (int it = 0; it < nIter; ++it) {
        if (it + 1 < nIter) issue_copy((it + 1) * BK, (it + 1) & 1);
        cp_commit();
        cp_wait1();
        __syncthreads();

        const uint32_t* As = dynsmem + (it & 1) * STG;
        const uint32_t* Bs = As + ASZ;

        #pragma unroll
        for (int ks = 0; ks < 4; ++ks) {
            int kc = ks * 8 + (lane & 3);
            uint32_t af[4][4], bf[4][2];
            #pragma unroll
            for (int mt = 0; mt < 4; ++mt) {
                int mr = wm * 64 + mt * 16 + (lane >> 2);
                af[mt][0] = As[mr * ASTR + kc];
                af[mt][1] = As[(mr + 8) * ASTR + kc];
                af[mt][2] = As[mr * ASTR + kc + 4];
                af[mt][3] = As[(mr + 8) * ASTR + kc + 4];
            }
            #pragma unroll
            for (int nt = 0; nt < 4; ++nt) {
                int nc = wn * 32 + nt * 8 + (lane >> 2);
                bf[nt][0] = Bs[kc * 136 + nc];
                bf[nt][1] = Bs[(kc + 4) * 136 + nc];
            }
            #pragma unroll
            for (int mt = 0; mt < 4; ++mt)
                #pragma unroll
                for (int nt = 0; nt < 4; ++nt)
                    mma_tf32(acc[mt][nt][0], acc[mt][nt][1],
                             acc[mt][nt][2], acc[mt][nt][3],
                             af[mt][0], af[mt][1], af[mt][2], af[mt][3],
                             bf[nt][0], bf[nt][1]);
        }
        __syncthreads();
    }

    #pragma unroll
    for (int mt = 0; mt < 4; ++mt) {
        int mr = row0 + wm * 64 + mt * 16 + (lane >> 2);
        #pragma unroll
        for (int nt = 0; nt < 4; ++nt) {
            int nc = col0 + wn * 32 + nt * 8 + 2 * (lane & 3);
            float b0 = bias[nc], b1 = bias[nc + 1];
            *(float2*)(C + (size_t)mr * D + nc) =
                make_float2(acc[mt][nt][0] + b0, acc[mt][nt][1] + b1);
            *(float2*)(C + (size_t)(mr + 8) * D + nc) =
                make_float2(acc[mt][nt][2] + b0, acc[mt][nt][3] + b1);
        }
    }
}

// ---------------------------------------------------------------------------
// Fused flash attention per (b,h): ctx = softmax(Q K^T / 8) V
// grid: (L/128, BH), 256 threads (8 warps, warp w owns q-rows w*16..w*16+15).
// Q tile 128x64 (frags in regs), KV chunks of 64 keys, double-buffered cp.async.
// smem: QP 128x68 (Q then P), K 2x64x68, V 2x64x72  = 106496 bytes.
// ---------------------------------------------------------------------------
constexpr int FQ   = 128;
constexpr int FKV  = 64;
constexpr int QSTR = 68;
constexpr int VSTR = 72;
constexpr int F_QP = FQ * QSTR;             // 8704 words
constexpr int F_K  = FKV * QSTR;            // 4352 words / buf
constexpr int F_V  = FKV * VSTR;            // 4608 words / buf
constexpr int FSMEM_BYTES = (F_QP + 2 * F_K + 2 * F_V) * 4;   // 106496

__global__ __launch_bounds__(256) void flash_kernel(
    const float* __restrict__ q, const float* __restrict__ k,
    const float* __restrict__ v, float* __restrict__ ctx, int Sk) {
    extern __shared__ float fsm[];
    uint32_t smem0 = (uint32_t)__cvta_generic_to_shared(fsm);

    int tid = threadIdx.x, lane = tid & 31, warp = tid >> 5;
    int q0 = blockIdx.x * FQ;
    int bh = blockIdx.y, b = bh / H, h = bh % H;
    const float* Qg = q + ((size_t)(b * L) + q0) * D + h * DH;
    const float* Kg = k + (size_t)b * Sk * D + h * DH;
    const float* Vg = v + (size_t)b * Sk * D + h * DH;

    int rbase = tid >> 4, c4 = (tid & 15) * 4;

    // Q load (128 rows x 64)
    #pragma unroll
    for (int i = 0; i < 8; ++i) {
        int r = i * 16 + rbase;
        cpasync16(smem0 + (uint32_t)(r * QSTR + c4) * 4u, Qg + (size_t)r * D + c4);
    }
    auto ldK = [&](int it, int buf) {
        const float* src = Kg + (size_t)it * FKV * D;
        uint32_t base = smem0 + (uint32_t)(F_QP + buf * F_K) * 4u;
        #pragma unroll
        for (int i = 0; i < 4; ++i) {
            int r = i * 16 + rbase;
            cpasync16(base + (uint32_t)(r * QSTR + c4) * 4u, src + (size_t)r * D + c4);
        }
    };
    auto ldV = [&](int it, int buf) {
        const float* src = Vg + (size_t)it * FKV * D;
        uint32_t base = smem0 + (uint32_t)(F_QP + 2 * F_K + buf * F_V) * 4u;
        #pragma unroll
        for (int i = 0; i < 4; ++i) {
            int r = i * 16 + rbase;
            cpasync16(base + (uint32_t)(r * VSTR + c4) * 4u, src + (size_t)r * D + c4);
        }
    };
    ldK(0, 0); ldV(0, 0);
    cp_commit();
    cp_wait0();
    __syncthreads();

    int c = lane & 3, rq = lane >> 2;
    int prow = warp * 16 + rq;

    // Q fragments (scale 1/8 folded in; *0.125f is exact)
    uint32_t qf[8][4];
    {
        const uint32_t* Qu = (const uint32_t*)fsm;
        #pragma unroll
        for (int kk = 0; kk < 8; ++kk) {
            qf[kk][0] = __float_as_uint(0.125f * __uint_as_float(Qu[prow * QSTR + kk * 8 + c]));
            qf[kk][1] = __float_as_uint(0.125f * __uint_as_float(Qu[(prow + 8) * QSTR + kk * 8 + c]));
            qf[kk][2] = __float_as_uint(0.125f * __uint_as_float(Qu[prow * QSTR + kk * 8 + c + 4]));
            qf[kk][3] = __float_as_uint(0.125f * __uint_as_float(Qu[(prow + 8) * QSTR + kk * 8 + c + 4]));
        }
    }
    __syncthreads();   // Qs region now reusable as P

    float of[8][4];
    #pragma unroll
    for (int nt = 0; nt < 8; ++nt)
        #pragma unroll
        for (int i = 0; i < 4; ++i) of[nt][i] = 0.f;
    float m0 = -3.0e38f, m1 = -3.0e38f, l0 = 0.f, l1 = 0.f;

    int nIter = Sk / FKV;
    for (int it = 0; it < nIter; ++it) {
        int cur = it & 1, nxt = cur ^ 1;
        if (it + 1 < nIter) { ldK(it + 1, nxt); ldV(it + 1, nxt); }
        cp_commit();

        const uint32_t* Ks = (const uint32_t*)fsm + F_QP + cur * F_K;
        const uint32_t* Vs = (const uint32_t*)fsm + F_QP + 2 * F_K + cur * F_V;

        // S = (Q/8) K^T  : 16 rows x 64 keys per warp
        float sf[8][4];
        #pragma unroll
        for (int nt = 0; nt < 8; ++nt)
            #pragma unroll
            for (int i = 0; i < 4; ++i) sf[nt][i] = 0.f;
        #pragma unroll
        for (int kk = 0; kk < 8; ++kk) {
            #pragma unroll
            for (int nt = 0; nt < 8; ++nt) {
                uint32_t b0 = Ks[(nt * 8 + rq) * QSTR + kk * 8 + c];
                uint32_t b1 = Ks[(nt * 8 + rq) * QSTR + kk * 8 + c + 4];
                mma_tf32(sf[nt][0], sf[nt][1], sf[nt][2], sf[nt][3],
                         qf[kk][0], qf[kk][1], qf[kk][2], qf[kk][3], b0, b1);
            }
        }

        // online softmax
        float mx0 = -3.0e38f, mx1 = -3.0e38f;
        #pragma unroll
        for (int nt = 0; nt < 8; ++nt) {
            mx0 = fmaxf(mx0, fmaxf(sf[nt][0], sf[nt][1]));
            mx1 = fmaxf(mx1, fmaxf(sf[nt][2], sf[nt][3]));
        }
        mx0 = fmaxf(mx0, __shfl_xor_sync(0xffffffffu, mx0, 1));
        mx0 = fmaxf(mx0, __shfl_xor_sync(0xffffffffu, mx0, 2));
        mx1 = fmaxf(mx1, __shfl_xor_sync(0xffffffffu, mx1, 1));
        mx1 = fmaxf(mx1, __shfl_xor_sync(0xffffffffu, mx1, 2));
        float mn0 = fmaxf(m0, mx0), mn1 = fmaxf(m1, mx1);
        float f0 = __expf(m0 - mn0), f1 = __expf(m1 - mn1);

        float* Ps = fsm;
        float rs0 = 0.f, rs1 = 0.f;
        #pragma unroll
        for (int nt = 0; nt < 8; ++nt) {
            float p0 = __expf(sf[nt][0] - mn0);
            float p1 = __expf(sf[nt][1] - mn0);
            float p2 = __expf(sf[nt][2] - mn1);
            float p3 = __expf(sf[nt][3] - mn1);
            rs0 += p0 + p1; rs1 += p2 + p3;
            *(float2*)&Ps[prow * QSTR + nt * 8 + 2 * c] = make_float2(p0, p1);
            *(float2*)&Ps[(prow + 8) * QSTR + nt * 8 + 2 * c] = make_float2(p2, p3);
        }
        rs0 += __shfl_xor_sync(0xffffffffu, rs0, 1);
        rs0 += __shfl_xor_sync(0xffffffffu, rs0, 2);
        rs1 += __shfl_xor_sync(0xffffffffu, rs1, 1);
        rs1 += __shfl_xor_sync(0xffffffffu, rs1, 2);
        l0 = l0 * f0 + rs0; l1 = l1 * f1 + rs1;
        m0 = mn0; m1 = mn1;
        #pragma unroll
        for (int nt = 0; nt < 8; ++nt) {
            of[nt][0] *= f0; of[nt][1] *= f0;
            of[nt][2] *= f1; of[nt][3] *= f1;
        }
        __syncwarp();

        // O += P V   (contraction over 64 keys)
        const uint32_t* Pu = (const uint32_t*)fsm;
        #pragma unroll
        for (int kk = 0; kk < 8; ++kk) {
            uint32_t a0 = Pu[prow * QSTR + kk * 8 + c];
            uint32_t a1 = Pu[(prow + 8) * QSTR + kk * 8 + c];
            uint32_t a2 = Pu[prow * QSTR + kk * 8 + c + 4];
            uint32_t a3 = Pu[(prow + 8) * QSTR + kk * 8 + c + 4];
            #pragma unroll
            for (int nt = 0; nt < 8; ++nt) {
                uint32_t b0 = Vs[(kk * 8 + c) * VSTR + nt * 8 + rq];
                uint32_t b1 = Vs[(kk * 8 + c + 4) * VSTR + nt * 8 + rq];
                mma_tf32(of[nt][0], of[nt][1], of[nt][2], of[nt][3],
                         a0, a1, a2, a3, b0, b1);
            }
        }
        cp_wait0();
        __syncthreads();
    }

    float il0 = 1.f / l0, il1 = 1.f / l1;
    int rg = b * L + q0 + warp * 16 + rq;
    float* dst0 = ctx + (size_t)rg * D + h * DH;
    float* dst1 = ctx + (size_t)(rg + 8) * D + h * DH;
    #pragma unroll
    for (int nt = 0; nt < 8; ++nt) {
        *(float2*)(dst0 + nt * 8 + 2 * c) = make_float2(of[nt][0] * il0, of[nt][1] * il0);
        *(float2*)(dst1 + nt * 8 + 2 * c) = make_float2(of[nt][2] * il1, of[nt][3] * il1);
    }
}

// ---------------------------------------------------------------------------
// Row L2-normalize: y = x / ||x||
// ---------------------------------------------------------------------------
__global__ __launch_bounds__(256) void rownorm_kernel(
    const float* __restrict__ x, float* __restrict__ y) {
    __shared__ float sh[256];
    size_t row = blockIdx.x;
    int tid = threadIdx.x;
    const float* xr = x + row * D;
    float* yr = y + row * D;
    float v0 = xr[tid], v1 = xr[tid + 256], v2 = xr[tid + 512];
    float ss = blockReduceSum(v0 * v0 + v1 * v1 + v2 * v2, sh);
    float inv = rsqrtf(ss);
    yr[tid] = v0 * inv; yr[tid + 256] = v1 * inv; yr[tid + 512] = v2 * inv;
}

// ---------------------------------------------------------------------------
// Top-8 per row of sim. jax.lax.top_k semantics: sorted desc, ties -> lower idx.
// ---------------------------------------------------------------------------
__global__ __launch_bounds__(256) void topk_kernel(
    const float* __restrict__ sim, int* __restrict__ out) {
    __shared__ float sv[256][KP];
    __shared__ int   si[256][KP];
    int row = blockIdx.x;
    int tid = threadIdx.x;
    const float* s = sim + (size_t)row * NDICT;
    float tv[KP]; int ti[KP];
    #pragma unroll
    for (int i = 0; i < KP; ++i) { tv[i] = -3.4e38f; ti[i] = 0x7fffffff; }
    for (int j4 = tid; j4 < NDICT / 4; j4 += 256) {
        float4 v4 = *(const float4*)(s + (size_t)j4 * 4);
        float vv[4] = {v4.x, v4.y, v4.z, v4.w};
        #pragma unroll
        for (int cc = 0; cc < 4; ++cc) {
            float v = vv[cc];
            if (v > tv[KP - 1]) {
                int j = j4 * 4 + cc;
                int p = KP - 1;
                while (p > 0 && v > tv[p - 1]) { tv[p] = tv[p - 1]; ti[p] = ti[p - 1]; --p; }
                tv[p] = v; ti[p] = j;
            }
        }
    }
    #pragma unroll
    for (int i = 0; i < KP; ++i) { sv[tid][i] = tv[i]; si[tid][i] = ti[i]; }
    __syncthreads();
    for (int st = 128; st >= 1; st >>= 1) {
        if (tid < st) {
            float mv[KP]; int mi[KP]; int pa = 0, pb = 0;
            #pragma unroll
            for (int o = 0; o < KP; ++o) {
                float va = sv[tid][pa], vb = sv[tid + st][pb];
                int ia = si[tid][pa], ib = si[tid + st][pb];
                bool takeA = (va > vb) || (va == vb && ia <= ib);
                if (takeA) { mv[o] = va; mi[o] = ia; ++pa; }
                else       { mv[o] = vb; mi[o] = ib; ++pb; }
            }
            #pragma unroll
            for (int o = 0; o < KP; ++o) { sv[tid][o] = mv[o]; si[tid][o] = mi[o]; }
        }
        __syncthreads();
    }
    if (tid < KP) out[(size_t)row * KP + tid] = si[0][tid];
}

// ---------------------------------------------------------------------------
// Gather retrieved prototypes (UNnormalized dict rows) into [B*SKG, D]
// ---------------------------------------------------------------------------
__global__ __launch_bounds__(256) void gather_kernel(
    const float* __restrict__ dict, const int* __restrict__ topk,
    float* __restrict__ gfeats) {
    int r = blockIdx.x;
    int b = r >> 11;
    int pos = r & 2047;
    int idx = topk[((size_t)(b * L + (pos >> 3))) * KP + (pos & 7)];
    const float* src = dict + (size_t)idx * D;
    float* dst = gfeats + (size_t)r * D;
    for (int j = threadIdx.x; j < D / 4; j += 256)
        ((float4*)dst)[j] = ((const float4*)src)[j];
}

// ---------------------------------------------------------------------------
// y = LayerNorm(x + residual) * g + beta
// ---------------------------------------------------------------------------
__global__ __launch_bounds__(256) void residual_ln_kernel(
    const float* __restrict__ x, const float* __restrict__ res,
    const float* __restrict__ g, const float* __restrict__ beta,
    float* __restrict__ out) {
    __shared__ float sh[256];
    size_t base = (size_t)blockIdx.x * D;
    int tid = threadIdx.x;
    float v[3];
    #pragma unroll
    for (int t = 0; t < 3; ++t) {
        int i = tid + (t << 8);
        v[t] = x[base + i] + res[base + i];
    }
    float mean = blockReduceSum(v[0] + v[1] + v[2], sh) * (1.0f / 768.0f);
    float d0 = v[0] - mean, d1 = v[1] - mean, d2 = v[2] - mean;
    float var = blockReduceSum(d0 * d0 + d1 * d1 + d2 * d2, sh) * (1.0f / 768.0f);
    float inv = rsqrtf(var + 1e-12f);
    #pragma unroll
    for (int t = 0; t < 3; ++t) {
        int i = tid + (t << 8);
        out[base + i] = (v[t] - mean) * inv * g[i] + beta[i];
    }
}

// ---------------------------------------------------------------------------
// Final: out_ln = LN(ll+lg); gate = sigmoid(out_ln.aug_w+aug_b+local.ori_w+ori_b)
//        result = gate*out_ln + (1-gate)*local
// ---------------------------------------------------------------------------
__global__ __launch_bounds__(256) void final_kernel(
    const float* __restrict__ ll, const float* __restrict__ lg,
    const float* __restrict__ local, const float* __restrict__ g,
    const float* __restrict__ beta, const float* __restrict__ aug_w,
    const float* __restrict__ aug_b, const float* __restrict__ ori_w,
    const float* __restrict__ ori_b, float* __restrict__ out) {
    __shared__ float sh[256];
    size_t base = (size_t)blockIdx.x * D;
    int tid = threadIdx.x;
    float s[3], lf[3];
    #pragma unroll
    for (int t = 0; t < 3; ++t) {
        int i = tid + (t << 8);
        s[t] = ll[base + i] + lg[base + i];
        lf[t] = local[base + i];
    }
    float mean = blockReduceSum(s[0] + s[1] + s[2], sh) * (1.0f / 768.0f);
    float d0 = s[0] - mean, d1 = s[1] - mean, d2 = s[2] - mean;
    float var = blockReduceSum(d0 * d0 + d1 * d1 + d2 * d2, sh) * (1.0f / 768.0f);
    float inv = rsqrtf(var + 1e-12f);
    float o[3];
    float dsum = 0.f;
    #pragma unroll
    for (int t = 0; t < 3; ++t) {
        int i = tid + (t << 8);
        o[t] = (s[t] - mean) * inv * g[i] + beta[i];
        dsum += o[t] * aug_w[i] + lf[t] * ori_w[i];
    }
    dsum = blockReduceSum(dsum, sh);
    float gate = 1.0f / (1.0f + expf(-(dsum + aug_b[0] + ori_b[0])));
    #pragma unroll
    for (int t = 0; t < 3; ++t) {
        int i = tid + (t << 8);
        out[base + i] = gate * o[t] + (1.0f - gate) * lf[t];
    }
}

// ---------------------------------------------------------------------------
// Host launcher
// ---------------------------------------------------------------------------
extern "C" void kernel_launch(void* const* d_in, const int* in_sizes, int n_in,
                              void* d_out, int out_size) {
    (void)n_in; (void)out_size;
    const float* local = (const float*)d_in[0];
    const float* dict  = (const float*)d_in[1];

    bool sig = (in_sizes[3] == 768);
    const float *W[2][4], *Bi[2][4], *LNG[2], *LNB[2];
    for (int p = 0; p < 2; ++p) {
        int base = 2 + p * 10;
        if (sig) {
            for (int j = 0; j < 4; ++j) {
                W[p][j]  = (const float*)d_in[base + 2 * j];
                Bi[p][j] = (const float*)d_in[base + 2 * j + 1];
            }
        } else {
            for (int j = 0; j < 4; ++j) {
                W[p][j]  = (const float*)d_in[base + j];
                Bi[p][j] = (const float*)d_in[base + 4 + j];
            }
        }
        LNG[p] = (const float*)d_in[base + 8];
        LNB[p] = (const float*)d_in[base + 9];
    }
    const float* ln_g = (const float*)d_in[22];
    const float* ln_b = (const float*)d_in[23];
    const float *aug_w, *aug_b, *ori_w, *ori_b;
    if (in_sizes[25] == 1) {
        aug_w = (const float*)d_in[24]; aug_b = (const float*)d_in[25];
        ori_w = (const float*)d_in[26]; ori_b = (const float*)d_in[27];
    } else {
        aug_w = (const float*)d_in[24]; ori_w = (const float*)d_in[25];
        aug_b = (const float*)d_in[26]; ori_b = (const float*)d_in[27];
    }

    float *p_tnorm, *p_gnorm, *p_sim, *p_gfeats, *p_q, *p_q2, *p_k, *p_v;
    float *p_ctx, *p_ctx2, *p_proj, *p_proj2, *p_ll, *p_lg;
    int* p_topk;
    cudaGetSymbolAddress((void**)&p_tnorm, g_tnorm);
    cudaGetSymbolAddress((void**)&p_gnorm, g_gnorm);
    cudaGetSymbolAddress((void**)&p_sim, g_sim);
    cudaGetSymbolAddress((void**)&p_topk, g_topk);
    cudaGetSymbolAddress((void**)&p_gfeats, g_gfeats);
    cudaGetSymbolAddress((void**)&p_q, g_q);
    cudaGetSymbolAddress((void**)&p_q2, g_q2);
    cudaGetSymbolAddress((void**)&p_k, g_k);
    cudaGetSymbolAddress((void**)&p_v, g_v);
    cudaGetSymbolAddress((void**)&p_ctx, g_ctx);
    cudaGetSymbolAddress((void**)&p_ctx2, g_ctx2);
    cudaGetSymbolAddress((void**)&p_proj, g_proj);
    cudaGetSymbolAddress((void**)&p_proj2, g_proj2);
    cudaGetSymbolAddress((void**)&p_ll, g_ll);
    cudaGetSymbolAddress((void**)&p_lg, g_lg);

    const int SM_SIM = 2 * (128 * 36 + 128 * 36) * 4;   // 73728
    const int SM_NN  = 2 * (128 * 36 + 32 * 136) * 4;   // 71680

    cudaFuncSetAttribute(tf32gemm_nt_split,
                         cudaFuncAttributeMaxDynamicSharedMemorySize, SM_SIM);
    cudaFuncSetAttribute(tf32gemm_nn_multi,
                         cudaFuncAttributeMaxDynamicSharedMemorySize, SM_NN);
    cudaFuncSetAttribute(flash_kernel,
                         cudaFuncAttributeMaxDynamicSharedMemorySize, FSMEM_BYTES);

    // 1) normalize
    rownorm_kernel<<<NDICT, 256>>>(dict, p_gnorm);
    rownorm_kernel<<<M, 256>>>(local, p_tnorm);

    // 2) sim = tnorm @ gnorm^T (3xTF32, top-k safe)
    tf32gemm_nt_split<<<dim3(NDICT / 128, M / 128), 256, SM_SIM>>>(
        p_tnorm, p_gnorm, p_sim, D, D, D, NDICT);

    // 3) top-8, gather
    topk_kernel<<<M, 256>>>(p_sim, p_topk);
    gather_kernel<<<B * SKG, 256>>>(dict, p_topk, p_gfeats);

    // 4) merged small projections: ll Q,K,V + lg Q (all read `local`)
    {
        Ptrs4 p;
        p.A[0] = local;    p.A[1] = local;    p.A[2] = local;    p.A[3] = local;
        p.W[0] = W[0][0];  p.W[1] = W[0][1];  p.W[2] = W[0][2];  p.W[3] = W[1][0];
        p.bias[0] = Bi[0][0]; p.bias[1] = Bi[0][1]; p.bias[2] = Bi[0][2]; p.bias[3] = Bi[1][0];
        p.C[0] = p_q;      p.C[1] = p_k;      p.C[2] = p_v;      p.C[3] = p_q2;
        tf32gemm_nn_multi<<<dim3(24, M / 128), 256, SM_NN>>>(p);
    }

    // 5) ll fused attention
    flash_kernel<<<dim3(L / FQ, BH), 256, FSMEM_BYTES>>>(p_q, p_k, p_v, p_ctx, L);

    // 6) lg K,V projections over gathered prototypes
    {
        Ptrs4 p;
        p.A[0] = p_gfeats; p.A[1] = p_gfeats; p.A[2] = p_gfeats; p.A[3] = p_gfeats;
        p.W[0] = W[1][1];  p.W[1] = W[1][2];  p.W[2] = W[1][1];  p.W[3] = W[1][2];
        p.bias[0] = Bi[1][1]; p.bias[1] = Bi[1][2]; p.bias[2] = Bi[1][1]; p.bias[3] = Bi[1][2];
        p.C[0] = p_k;      p.C[1] = p_v;      p.C[2] = p_k;      p.C[3] = p_v;
        tf32gemm_nn_multi<<<dim3(12, (B * SKG) / 128), 256, SM_NN>>>(p);
    }

    // 7) lg fused attention
    flash_kernel<<<dim3(L / FQ, BH), 256, FSMEM_BYTES>>>(p_q2, p_k, p_v, p_ctx2, SKG);

    // 8) merged output projections
    {
        Ptrs4 p;
        p.A[0] = p_ctx;    p.A[1] = p_ctx2;   p.A[2] = p_ctx;    p.A[3] = p_ctx2;
        p.W[0] = W[0][3];  p.W[1] = W[1][3];  p.W[2] = W[0][3];  p.W[3] = W[1][3];
        p.bias[0] = Bi[0][3]; p.bias[1] = Bi[1][3]; p.bias[2] = Bi[0][3]; p.bias[3] = Bi[1][3];
        p.C[0] = p_proj;   p.C[1] = p_proj2;  p.C[2] = p_proj;   p.C[3] = p_proj2;
        tf32gemm_nn_multi<<<dim3(12, M / 128), 256, SM_NN>>>(p);
    }

    // 9) residual + LN for both branches
    residual_ln_kernel<<<M, 256>>>(p_proj, local, LNG[0], LNB[0], p_ll);
    residual_ln_kernel<<<M, 256>>>(p_proj2, local, LNG[1], LNB[1], p_lg);

    // 10) final LN + gating
    final_kernel<<<M, 256>>>(p_ll, p_lg, local, ln_g, ln_b,
                             aug_w, aug_b, ori_w, ori_b, (float*)d_out);
}